// round 11
// baseline (speedup 1.0000x reference)
#include <cuda_runtime.h>
#include <cuda_fp16.h>
#include <cstdint>

// Problem constants (fixed by the dataset)
#define C_NV 100000
#define C_NC 400000
#define C_NU 64
#define C_E  1200000
#define C_D  128
#define C_NN (C_NC + C_NV)          // concatenated node count for degree/scan

// ---------------- scratch (device globals; no allocation allowed) ----------
__device__ __align__(16) __half g_hc[(size_t)C_NC * C_D];  // clause message means
__device__ __align__(16) __half g_hv[(size_t)C_NV * C_D];  // var message means
__device__ __align__(16) __half g_Pv[(size_t)C_NV * C_D];  // var_emb @ W_vc[4:132]
__device__ __align__(16) __half g_Pc[(size_t)C_NC * C_D];  // clause_emb @ W_cv[4:132]
__device__ float g_Qc[C_NU * C_D];             // ctx_emb @ W_c[144:272]
__device__ float g_Qv[C_NU * C_D];             // ctx_emb @ W_v[144:272]
__device__ float g_ctx_acc[2 * C_NU * C_D];    // [clause sums | var sums]
__device__ float g_ctx_cnt[2 * C_NU];

// CSR edge binning: packed records {src, pad, es01(h2), es23(h2)} = 16 B
__device__ int   g_deg[C_NN];                  // degrees -> exclusive scan (base)
__device__ int   g_fill[C_NN];                 // scatter cursors (== deg after)
__device__ int   g_bsum[256];                  // scan block sums
__device__ __align__(16) uint4 g_sedge1[C_E];  // dir1 (var->clause)
__device__ __align__(16) uint4 g_sedge2[C_E];  // dir2 (clause->var)

// Transposed tf32-rounded weights: layout [n (0..127)][k (0..K-1)], fp32 bits
__device__ __align__(16) float g_Bvc[128 * 128];
__device__ __align__(16) float g_Bcv[128 * 128];
__device__ __align__(16) float g_Bc[128 * 272];
__device__ __align__(16) float g_Bv[128 * 272];

static __device__ __forceinline__ float lrelu(float x) {
    return x >= 0.f ? x : 0.1f * x;
}

static __device__ __forceinline__ uint32_t smem_u32(const void* p) {
    uint32_t a;
    asm("{ .reg .u64 t; cvta.to.shared.u64 t, %1; cvt.u32.u64 %0, t; }"
        : "=r"(a) : "l"(p));
    return a;
}

static __device__ __forceinline__ uint32_t f2tf32(float f) {
    uint32_t u;
    asm("cvt.rna.tf32.f32 %0, %1;" : "=r"(u) : "f"(f));
    return u;
}

#define LDS32(d, addr)                                                         \
    asm volatile("ld.shared.b32 %0, [%1];" : "=r"(d) : "r"(addr))

// mma.sync m16n8k8 tf32 -> fp32
#define MMATF32(c, a, b0, b1)                                                  \
    asm volatile(                                                              \
        "mma.sync.aligned.m16n8k8.row.col.f32.tf32.tf32.f32 "                  \
        "{%0,%1,%2,%3}, {%4,%5,%6,%7}, {%8,%9}, {%0,%1,%2,%3};"                \
        : "+f"((c)[0]), "+f"((c)[1]), "+f"((c)[2]), "+f"((c)[3])               \
        : "r"((a)[0]), "r"((a)[1]), "r"((a)[2]), "r"((a)[3]),                  \
          "r"(b0), "r"(b1))

#define CP_ASYNC16(dst, src, sz)                                               \
    asm volatile("cp.async.cg.shared.global [%0], [%1], 16, %2;"               \
                 :: "r"(dst), "l"(src), "r"(sz))
#define CP_COMMIT() asm volatile("cp.async.commit_group;" ::: "memory")
#define CP_WAIT(n)  asm volatile("cp.async.wait_group %0;" :: "n"(n) : "memory")

// ---------------- zero small accumulators ------------------------------------
__global__ void zero_small(int* deg, int* fill, float* cacc, float* ccnt)
{
    int i = blockIdx.x * blockDim.x + threadIdx.x;
    int stride = gridDim.x * blockDim.x;
    for (int j = i; j < C_NN; j += stride) { deg[j] = 0; fill[j] = 0; }
    for (int j = i; j < 2 * C_NU * C_D; j += stride) cacc[j] = 0.f;
    if (i < 2 * C_NU) ccnt[i] = 0.f;
}

// ---------------- histogram of destinations ---------------------------------
__global__ void hist_kernel(int E, const int* __restrict__ dst1,
                            const int* __restrict__ dst2, int* __restrict__ deg)
{
    int i = blockIdx.x * blockDim.x + threadIdx.x;
    if (i < E)          atomicAdd(&deg[dst1[i]], 1);
    else if (i < 2 * E) atomicAdd(&deg[C_NC + dst2[i - E]], 1);
}

// ---------------- exclusive scan (3 kernels, 4096/block) ---------------------
__global__ void scanA(const int* __restrict__ deg, int n,
                      int* __restrict__ base, int* __restrict__ bsum)
{
    __shared__ int tsum[256];
    const int t = threadIdx.x;
    const int b0 = blockIdx.x * 4096;
    int v[16];
    int s = 0;
#pragma unroll
    for (int j = 0; j < 16; j++) {
        int idx = b0 + t * 16 + j;
        v[j] = (idx < n) ? deg[idx] : 0;
        s += v[j];
    }
    tsum[t] = s;
    __syncthreads();
    for (int off = 1; off < 256; off <<= 1) {
        int u = (t >= off) ? tsum[t - off] : 0;
        __syncthreads();
        tsum[t] += u;
        __syncthreads();
    }
    int run = tsum[t] - s;
#pragma unroll
    for (int j = 0; j < 16; j++) {
        int idx = b0 + t * 16 + j;
        if (idx < n) base[idx] = run;
        run += v[j];
    }
    if (t == 255) bsum[blockIdx.x] = tsum[255];
}

__global__ void scanB(int* bsum, int nb)
{
    if (threadIdx.x == 0 && blockIdx.x == 0) {
        int r = 0;
        for (int i = 0; i < nb; i++) { int d = bsum[i]; bsum[i] = r; r += d; }
    }
}

__global__ void scanC(int* __restrict__ base, const int* __restrict__ bsum, int n)
{
    int i = blockIdx.x * blockDim.x + threadIdx.x;
    if (i < n) base[i] += bsum[i >> 12];
}

// ---------------- scatter edges into destination order ----------------------
__global__ void scatter_kernel(
    int E,
    const int* __restrict__ src1, const int* __restrict__ dst1,
    const float4* __restrict__ es1,
    const int* __restrict__ src2, const int* __restrict__ dst2,
    const float4* __restrict__ es2,
    const int* __restrict__ base, int* __restrict__ fill,
    uint4* __restrict__ sedge1, uint4* __restrict__ sedge2)
{
    int i = blockIdx.x * blockDim.x + threadIdx.x;
    if (i < E) {
        int d = dst1[i];
        int p = base[d] + atomicAdd(&fill[d], 1);
        float4 ev = es1[i];
        __half2 h01 = __floats2half2_rn(ev.x, ev.y);
        __half2 h23 = __floats2half2_rn(ev.z, ev.w);
        uint4 rec;
        rec.x = (uint32_t)src1[i];
        rec.y = 0u;
        rec.z = *reinterpret_cast<uint32_t*>(&h01);
        rec.w = *reinterpret_cast<uint32_t*>(&h23);
        sedge1[p] = rec;
    } else if (i < 2 * E) {
        int e = i - E;
        int d = C_NC + dst2[e];
        int p = base[d] + atomicAdd(&fill[d], 1) - E;
        float4 ev = es2[e];
        __half2 h01 = __floats2half2_rn(ev.x, ev.y);
        __half2 h23 = __floats2half2_rn(ev.z, ev.w);
        uint4 rec;
        rec.x = (uint32_t)src2[e];
        rec.y = 0u;
        rec.z = *reinterpret_cast<uint32_t*>(&h01);
        rec.w = *reinterpret_cast<uint32_t*>(&h23);
        sedge2[p] = rec;
    }
}

// ---------------- CSR aggregate: warp per destination node ------------------
__global__ __launch_bounds__(256) void agg_kernel(
    int N0, int baseoff, int posoff,
    const int* __restrict__ base, const int* __restrict__ fill,
    const uint4* __restrict__ sedge,
    const __half* __restrict__ P,
    const float* __restrict__ W1, const float* __restrict__ b,
    __half* __restrict__ outh)
{
    const int warp = blockIdx.x * 8 + (threadIdx.x >> 5);
    if (warp >= N0) return;
    const int lane = threadIdx.x & 31;
    const int c = lane * 4;

    float w[4][4], bb[4];
#pragma unroll
    for (int r = 0; r < 4; r++)
#pragma unroll
        for (int i = 0; i < 4; i++)
            w[r][i] = W1[r * 128 + c + i];
#pragma unroll
    for (int i = 0; i < 4; i++) bb[i] = b[c + i];

    const int start = base[baseoff + warp] - posoff;
    const int deg   = fill[baseoff + warp];

    float s0 = 0.f, s1 = 0.f, s2 = 0.f, s3 = 0.f;

    auto edge_term = [&](uint4 rec, uint2 praw) {
        float2 e01 = __half22float2(*reinterpret_cast<__half2*>(&rec.z));
        float2 e23 = __half22float2(*reinterpret_cast<__half2*>(&rec.w));
        float2 p01 = __half22float2(*reinterpret_cast<__half2*>(&praw.x));
        float2 p23 = __half22float2(*reinterpret_cast<__half2*>(&praw.y));
        float m0 = bb[0], m1 = bb[1], m2 = bb[2], m3 = bb[3];
        m0 = fmaf(e01.x, w[0][0], m0); m0 = fmaf(e01.y, w[1][0], m0);
        m0 = fmaf(e23.x, w[2][0], m0); m0 = fmaf(e23.y, w[3][0], m0);
        m1 = fmaf(e01.x, w[0][1], m1); m1 = fmaf(e01.y, w[1][1], m1);
        m1 = fmaf(e23.x, w[2][1], m1); m1 = fmaf(e23.y, w[3][1], m1);
        m2 = fmaf(e01.x, w[0][2], m2); m2 = fmaf(e01.y, w[1][2], m2);
        m2 = fmaf(e23.x, w[2][2], m2); m2 = fmaf(e23.y, w[3][2], m2);
        m3 = fmaf(e01.x, w[0][3], m3); m3 = fmaf(e01.y, w[1][3], m3);
        m3 = fmaf(e23.x, w[2][3], m3); m3 = fmaf(e23.y, w[3][3], m3);
        s0 += lrelu(m0 + p01.x);
        s1 += lrelu(m1 + p01.y);
        s2 += lrelu(m2 + p23.x);
        s3 += lrelu(m3 + p23.y);
    };

    int j = 0;
    for (; j + 4 <= deg; j += 4) {
        uint4 r0 = sedge[start + j + 0];
        uint4 r1 = sedge[start + j + 1];
        uint4 r2 = sedge[start + j + 2];
        uint4 r3 = sedge[start + j + 3];
        uint2 q0 = *(const uint2*)(P + (size_t)r0.x * 128 + c);
        uint2 q1 = *(const uint2*)(P + (size_t)r1.x * 128 + c);
        uint2 q2 = *(const uint2*)(P + (size_t)r2.x * 128 + c);
        uint2 q3 = *(const uint2*)(P + (size_t)r3.x * 128 + c);
        edge_term(r0, q0);
        edge_term(r1, q1);
        edge_term(r2, q2);
        edge_term(r3, q3);
    }
    for (; j < deg; j++) {
        uint4 r0 = sedge[start + j];
        uint2 q0 = *(const uint2*)(P + (size_t)r0.x * 128 + c);
        edge_term(r0, q0);
    }

    float inv = (deg > 0) ? (1.f / (float)deg) : 0.f;
    __half2 o01 = __floats2half2_rn(s0 * inv, s1 * inv);
    __half2 o23 = __floats2half2_rn(s2 * inv, s3 * inv);
    uint2 pk;
    pk.x = *reinterpret_cast<uint32_t*>(&o01);
    pk.y = *reinterpret_cast<uint32_t*>(&o23);
    *(uint2*)(outh + (size_t)warp * 128 + c) = pk;
}

// ---------------- weight transpose + tf32 rounding --------------------------
__global__ void wprep(const float* __restrict__ Wvc, const float* __restrict__ Wcv,
                      const float* __restrict__ Wc,  const float* __restrict__ Wv)
{
    int i = blockIdx.x * blockDim.x + threadIdx.x;
    if (i >= 102400) return;
    float w;
    float* dst;
    int di;
    if (i < 16384) {                       // vc: K=128, W rows 4..131
        int n = i >> 7, k = i & 127;
        w = Wvc[(4 + k) * 128 + n];
        dst = g_Bvc; di = n * 128 + k;
    } else if (i < 32768) {                // cv: K=128, W rows 4..131
        int j = i - 16384;
        int n = j >> 7, k = j & 127;
        w = Wcv[(4 + k) * 128 + n];
        dst = g_Bcv; di = n * 128 + k;
    } else if (i < 67584) {                // c: K=272, W rows {0..143, 272..399}
        int j = i - 32768;
        int n = j / 272, k = j % 272;
        int kk = (k < 144) ? k : k + 128;
        w = Wc[kk * 128 + n];
        dst = g_Bc; di = n * 272 + k;
    } else {                               // v: K=272
        int j = i - 67584;
        int n = j / 272, k = j % 272;
        int kk = (k < 144) ? k : k + 128;
        w = Wv[kk * 128 + n];
        dst = g_Bv; di = n * 272 + k;
    }
    uint32_t t = f2tf32(w);
    dst[di] = __uint_as_float(t);
}

// ---------------- TF32 GEMM (deep pipeline, BM=64 x BN=128, 2 CTAs/SM) ------
// out[row,:] = act([Af | Ah | Ae] @ B^T + bias + Q[qidx[row]])
// A: LDG 2-ahead reg-prefetch -> cvt.rna.tf32 -> 2-buffer smem [64][36].
// B: cp.async 2-ahead -> 4-stage ring [128][36].
#define BK 32
#define AST 36
#define A_BUF (64 * AST * 4)               // 9216 B
#define B_STG (128 * AST * 4)              // 18432 B
#define B_BASE (2 * A_BUF)                 // 18432
#define SMEM_TOTAL_TC (B_BASE + 4 * B_STG) // 92160

__global__ __launch_bounds__(256, 2) void tc_gemm(
    int M,
    const float* __restrict__ Af, int KF,
    const void* __restrict__ Ah, int ah_half,
    const float* __restrict__ Ae,
    const float* __restrict__ Bt,          // [128][Ktot] tf32 bits
    int Ktot,
    const float* __restrict__ bias, const float* __restrict__ Q,
    const int* __restrict__ qidx, int act,
    float* __restrict__ out, __half* __restrict__ out16)
{
    extern __shared__ char smem[];
    const uint32_t sb = smem_u32(smem);
    const int tid  = threadIdx.x;
    const int wid  = tid >> 5;
    const int lane = tid & 31;

    const int row0 = blockIdx.x * 64;

    // A staging assignment: row r (0..63), 8-col quad q
    const int r = tid >> 2;
    const int q = (tid & 3) * 8;
    int grow = row0 + r;
    if (grow >= M) grow = M - 1;

    // B cp.async assignment: row brow (0..127), 16-float half bh
    const int brow = tid >> 1;
    const int bhf  = (tid & 1) * 16;
    const float* b_row = Bt + (size_t)brow * Ktot;

    const int nchunks = (Ktot + BK - 1) / BK;

    auto stage_b = [&](int c) {
        int s = c & 3;
        uint32_t dbase = sb + B_BASE + (uint32_t)s * B_STG +
                         (uint32_t)(brow * AST) * 4;
#pragma unroll
        for (int j2 = 0; j2 < 4; j2++) {
            int bq = bhf + j2 * 4;            // float offset within chunk
            int gk = c * BK + bq;
            int rem = Ktot - gk;
            int sz = rem >= 4 ? 16 : 0;       // Ktot multiple of 16
            int gks = (rem >= 4) ? gk : (Ktot - 4);
            CP_ASYNC16(dbase + (uint32_t)bq * 4, b_row + gks, sz);
        }
    };

    auto load_a = [&](int c, float4* va) {
        int k0 = c * BK;
#pragma unroll
        for (int j = 0; j < 2; j++) {
            int gk = k0 + q + j * 4;
            float4 v = make_float4(0.f, 0.f, 0.f, 0.f);
            if (gk < KF) {
                v = *(const float4*)(Af + (size_t)grow * KF + gk);
            } else if (gk < KF + 128) {
                if (ah_half) {
                    uint2 raw = *(const uint2*)((const __half*)Ah +
                                                (size_t)grow * 128 + (gk - KF));
                    float2 a01 = __half22float2(*reinterpret_cast<__half2*>(&raw.x));
                    float2 a23 = __half22float2(*reinterpret_cast<__half2*>(&raw.y));
                    v = make_float4(a01.x, a01.y, a23.x, a23.y);
                } else {
                    v = *(const float4*)((const float*)Ah +
                                         (size_t)grow * 128 + (gk - KF));
                }
            } else if (gk < Ktot) {
                v = *(const float4*)(Ae + (size_t)grow * 128 + (gk - KF - 128));
            }
            va[j] = v;
        }
    };

    // warp tile: 32(m) x 32(n); warps 2(m) x 4(n)
    const int m_base = (wid & 1) * 32;
    const int n_base = (wid >> 1) * 32;
    float acc[2][4][4];
#pragma unroll
    for (int mt = 0; mt < 2; mt++)
#pragma unroll
        for (int nt = 0; nt < 4; nt++)
            acc[mt][nt][0] = acc[mt][nt][1] = acc[mt][nt][2] = acc[mt][nt][3] = 0.f;

    const int gr = lane >> 2;     // 0..7
    const int tc = lane & 3;      // 0..3

    // ---- prologue: 2-ahead on both streams ----
    stage_b(0); CP_COMMIT();
    if (nchunks > 1) { stage_b(1); CP_COMMIT(); }
    float4 va[2][2];
    load_a(0, va[0]);
    if (nchunks > 1) load_a(1, va[1]);

    for (int c = 0; c < nchunks; c++) {
        const int abuf = c & 1;
        const uint32_t a_base = sb + (uint32_t)abuf * A_BUF;

        // cvt + store staged A chunk c (from reg set abuf)
#pragma unroll
        for (int j = 0; j < 2; j++) {
            uint4 t;
            t.x = f2tf32(va[abuf][j].x);
            t.y = f2tf32(va[abuf][j].y);
            t.z = f2tf32(va[abuf][j].z);
            t.w = f2tf32(va[abuf][j].w);
            *(uint4*)(smem + (a_base - sb) +
                      (uint32_t)(r * AST + q + j * 4) * 4) = t;
        }

        // 2-ahead prefetch: B(c+2) into ring stage (c+2)&3, A(c+2) into reg set
        if (c + 2 < nchunks) {
            stage_b(c + 2); CP_COMMIT();
            load_a(c + 2, va[abuf]);       // reg set just consumed
            CP_WAIT(2);                    // B(c) complete
        } else if (c + 1 < nchunks) {
            CP_WAIT(1);
        } else {
            CP_WAIT(0);
        }
        __syncthreads();

        const uint32_t b_base = sb + B_BASE + (uint32_t)(c & 3) * B_STG;

#pragma unroll
        for (int ks = 0; ks < 4; ks++) {
            const int k = ks * 8;
            uint32_t af[2][4];
#pragma unroll
            for (int mt = 0; mt < 2; mt++) {
                uint32_t r0 = a_base +
                    (uint32_t)((m_base + mt * 16 + gr) * AST + k + tc) * 4;
                uint32_t r1 = r0 + (uint32_t)(8 * AST) * 4;
                LDS32(af[mt][0], r0);
                LDS32(af[mt][1], r1);
                LDS32(af[mt][2], r0 + 16);
                LDS32(af[mt][3], r1 + 16);
            }
            uint32_t bf[4][2];
#pragma unroll
            for (int nt = 0; nt < 4; nt++) {
                uint32_t b0 = b_base +
                    (uint32_t)((n_base + nt * 8 + gr) * AST + k + tc) * 4;
                LDS32(bf[nt][0], b0);
                LDS32(bf[nt][1], b0 + 16);
            }
#pragma unroll
            for (int mt = 0; mt < 2; mt++)
#pragma unroll
                for (int nt = 0; nt < 4; nt++)
                    MMATF32(acc[mt][nt], af[mt], bf[nt][0], bf[nt][1]);
        }
        // A 2-buffer + B 4-stage ring: writer stages never collide with the
        // two live reader stages; one barrier per chunk suffices.
    }

    // ---- epilogue ----
#pragma unroll
    for (int mt = 0; mt < 2; mt++) {
        int row_a = row0 + m_base + mt * 16 + gr;
        int row_b = row_a + 8;
        const float* qa = nullptr;
        const float* qb = nullptr;
        if (Q) {
            if (row_a < M) qa = Q + (size_t)qidx[row_a] * 128;
            if (row_b < M) qb = Q + (size_t)qidx[row_b] * 128;
        }
#pragma unroll
        for (int nt = 0; nt < 4; nt++) {
            int col = n_base + nt * 8 + tc * 2;
            float b0 = 0.f, b1 = 0.f;
            if (bias) { b0 = bias[col]; b1 = bias[col + 1]; }
            if (row_a < M) {
                float v0 = acc[mt][nt][0] + b0;
                float v1 = acc[mt][nt][1] + b1;
                if (qa) { v0 += qa[col]; v1 += qa[col + 1]; }
                if (act) { v0 = lrelu(v0); v1 = lrelu(v1); }
                if (out16) {
                    *(__half2*)(out16 + (size_t)row_a * 128 + col) =
                        __floats2half2_rn(v0, v1);
                } else {
                    *(float2*)(out + (size_t)row_a * 128 + col) =
                        make_float2(v0, v1);
                }
            }
            if (row_b < M) {
                float v0 = acc[mt][nt][2] + b0;
                float v1 = acc[mt][nt][3] + b1;
                if (qb) { v0 += qb[col]; v1 += qb[col + 1]; }
                if (act) { v0 = lrelu(v0); v1 = lrelu(v1); }
                if (out16) {
                    *(__half2*)(out16 + (size_t)row_b * 128 + col) =
                        __floats2half2_rn(v0, v1);
                } else {
                    *(float2*)(out + (size_t)row_b * 128 + col) =
                        make_float2(v0, v1);
                }
            }
        }
    }
}

// ---------------- small SIMT GEMM (tiny Q precomputes, M=64,K=128) ----------
__global__ __launch_bounds__(256, 2) void fused_gemm(
    int M,
    const float* __restrict__ Ah, const float* __restrict__ Wh,
    float* __restrict__ out)
{
    __shared__ float As[64][16];
    __shared__ float Ws[16][128];

    const int t  = threadIdx.x;
    const int tx = t & 31;
    const int ty = t >> 5;
    const int row0 = blockIdx.x * 64;

    float acc[8][4];
#pragma unroll
    for (int r = 0; r < 8; r++)
        acc[r][0] = acc[r][1] = acc[r][2] = acc[r][3] = 0.f;

    const int aRow = t >> 2;
    const int aK   = (t & 3) * 4;
    const int wK   = t >> 4;
    const int wC   = (t & 15) * 8;

    int arow_g = row0 + aRow;
    if (arow_g >= M) arow_g = M - 1;

    for (int kk = 0; kk < 128; kk += 16) {
        __syncthreads();
        float4 av = *(const float4*)(Ah + (size_t)arow_g * 128 + kk + aK);
        *(float4*)&As[aRow][aK] = av;
        const float* wp = Wh + (size_t)(kk + wK) * 128 + wC;
        *(float4*)&Ws[wK][wC]     = *(const float4*)(wp);
        *(float4*)&Ws[wK][wC + 4] = *(const float4*)(wp + 4);
        __syncthreads();

#pragma unroll
        for (int k = 0; k < 16; k++) {
            float4 w = *(const float4*)&Ws[k][tx * 4];
#pragma unroll
            for (int r = 0; r < 8; r++) {
                float a = As[ty * 8 + r][k];
                acc[r][0] = fmaf(a, w.x, acc[r][0]);
                acc[r][1] = fmaf(a, w.y, acc[r][1]);
                acc[r][2] = fmaf(a, w.z, acc[r][2]);
                acc[r][3] = fmaf(a, w.w, acc[r][3]);
            }
        }
    }

#pragma unroll
    for (int r = 0; r < 8; r++) {
        int row = row0 + ty * 8 + r;
        if (row < M) {
            float4 v = make_float4(acc[r][0], acc[r][1], acc[r][2], acc[r][3]);
            *(float4*)(out + (size_t)row * 128 + tx * 4) = v;
        }
    }
}

// ---------------- segment mean into NU=64 contexts --------------------------
__global__ __launch_bounds__(128) void seg_mean_ctx(
    const float* __restrict__ srcm, const int* __restrict__ ids, int n,
    float* __restrict__ acc, float* __restrict__ cntp)
{
    __shared__ float sacc[64 * 128];
    __shared__ float scnt[64];
    const int t = threadIdx.x;
    for (int i = t; i < 64 * 128; i += 128) sacc[i] = 0.f;
    if (t < 64) scnt[t] = 0.f;
    __syncthreads();

    for (long r0 = (long)blockIdx.x * 4; r0 < n; r0 += (long)gridDim.x * 4) {
        float v[4]; int id[4]; int k = 0;
#pragma unroll
        for (int u = 0; u < 4; u++) {
            long r = r0 + u;
            if (r < n) {
                id[k] = ids[r];
                v[k]  = srcm[(size_t)r * 128 + t];
                k++;
            }
        }
        for (int u = 0; u < k; u++) {
            sacc[id[u] * 128 + t] += v[u];
            if (t == 0) scnt[id[u]] += 1.f;
        }
    }
    __syncthreads();
    for (int i = t; i < 64 * 128; i += 128) atomicAdd(&acc[i], sacc[i]);
    if (t < 64) atomicAdd(&cntp[t], scnt[t]);
}

// ---------------- context update (64 rows, K=400) ---------------------------
__global__ __launch_bounds__(128) void ctx_update(
    const float* __restrict__ ctx_feats,
    const float* __restrict__ ctx_emb,
    const float* __restrict__ acc,
    const float* __restrict__ cntp,
    const float* __restrict__ Wu,
    const float* __restrict__ bu,
    float* __restrict__ out)
{
    const int u = blockIdx.x;
    const int t = threadIdx.x;
    __shared__ float a[400];

    if (t < 16) a[t] = ctx_feats[u * 16 + t];
    float cc = fmaxf(cntp[u], 1.f);
    float cv = fmaxf(cntp[64 + u], 1.f);
    a[16 + t]  = acc[u * 128 + t] / cc;
    a[144 + t] = acc[64 * 128 + u * 128 + t] / cv;
    a[272 + t] = ctx_emb[u * 128 + t];
    __syncthreads();

    float s = bu[t];
    for (int k = 0; k < 400; k++) s = fmaf(a[k], Wu[k * 128 + t], s);
    out[(size_t)u * 128 + t] = lrelu(s);
}

// ---------------- launch ----------------------------------------------------
extern "C" void kernel_launch(void* const* d_in, const int* in_sizes, int n_in,
                              void* d_out, int out_size)
{
    const float* var_emb      = (const float*)d_in[0];
    const float* clause_emb   = (const float*)d_in[1];
    const float* ctx_emb      = (const float*)d_in[2];
    const float* var_feats    = (const float*)d_in[3];
    const float* clause_feats = (const float*)d_in[4];
    const float* ctx_feats    = (const float*)d_in[5];
    const float* edge_sat_vc  = (const float*)d_in[6];
    const float* edge_sat_cv  = (const float*)d_in[7];
    const float* W_vc         = (const float*)d_in[8];
    const float* b_vc         = (const float*)d_in[9];
    const float* W_cv         = (const float*)d_in[10];
    const float* b_cv         = (const float*)d_in[11];
    const float* W_c          = (const float*)d_in[12];
    const float* b_c          = (const float*)d_in[13];
    const float* W_v          = (const float*)d_in[14];
    const float* b_v          = (const float*)d_in[15];
    const float* W_u          = (const float*)d_in[16];
    const float* b_u          = (const float*)d_in[17];
    const int* assigns_src    = (const int*)d_in[18];
    const int* assigns_dst    = (const int*)d_in[19];
    const int* contains_src   = (const int*)d_in[20];
    const int* contains_dst   = (const int*)d_in[21];
    const int* var_ctx        = (const int*)d_in[22];
    const int* clause_ctx     = (const int*)d_in[23];

    const int NV = in_sizes[0] / C_D;
    const int NC = in_sizes[1] / C_D;
    const int E  = in_sizes[18];
    const int NN = NC + NV;

    float *Qc, *Qv, *cacc, *ccnt;
    __half *Pv, *Pc, *hc, *hv;
    cudaGetSymbolAddress((void**)&hc,   g_hc);
    cudaGetSymbolAddress((void**)&hv,   g_hv);
    cudaGetSymbolAddress((void**)&Pv,   g_Pv);
    cudaGetSymbolAddress((void**)&Pc,   g_Pc);
    cudaGetSymbolAddress((void**)&Qc,   g_Qc);
    cudaGetSymbolAddress((void**)&Qv,   g_Qv);
    cudaGetSymbolAddress((void**)&cacc, g_ctx_acc);
    cudaGetSymbolAddress((void**)&ccnt, g_ctx_cnt);

    int *deg, *fill, *bsum;
    uint4 *sedge1, *sedge2;
    cudaGetSymbolAddress((void**)&deg,    g_deg);
    cudaGetSymbolAddress((void**)&fill,   g_fill);
    cudaGetSymbolAddress((void**)&bsum,   g_bsum);
    cudaGetSymbolAddress((void**)&sedge1, g_sedge1);
    cudaGetSymbolAddress((void**)&sedge2, g_sedge2);

    float *Bvc, *Bcv, *Bc, *Bv;
    cudaGetSymbolAddress((void**)&Bvc, g_Bvc);
    cudaGetSymbolAddress((void**)&Bcv, g_Bcv);
    cudaGetSymbolAddress((void**)&Bc,  g_Bc);
    cudaGetSymbolAddress((void**)&Bv,  g_Bv);

    float* out = (float*)d_out;

    cudaFuncSetAttribute(tc_gemm, cudaFuncAttributeMaxDynamicSharedMemorySize,
                         SMEM_TOTAL_TC);

    const int nb = (NN + 4095) / 4096;   // scan blocks

    // 1. zero small accumulators (deg, fill, ctx)
    zero_small<<<512, 256>>>(deg, fill, cacc, ccnt);
    // 2. weight transpose + tf32 rounding
    wprep<<<(102400 + 255) / 256, 256>>>(W_vc, W_cv, W_c, W_v);
    // 3. P_v = var_emb @ W_vc[4:132]   (TF32, fp16 out)
    tc_gemm<<<(NV + 63) / 64, 256, SMEM_TOTAL_TC>>>(
        NV, nullptr, 0, var_emb, 0, nullptr,
        Bvc, 128, nullptr, nullptr, nullptr, 0, nullptr, Pv);
    // 4. P_c = clause_emb @ W_cv[4:132] (TF32, fp16 out) <-- ncu control point
    tc_gemm<<<(NC + 63) / 64, 256, SMEM_TOTAL_TC>>>(
        NC, nullptr, 0, clause_emb, 0, nullptr,
        Bcv, 128, nullptr, nullptr, nullptr, 0, nullptr, Pc);

    // 5. degree histogram (both directions)
    hist_kernel<<<(2 * E + 255) / 256, 256>>>(E, assigns_dst, contains_dst, deg);
    // 6-8. exclusive scan deg -> base (in place)
    scanA<<<nb, 256>>>(deg, NN, deg, bsum);
    scanB<<<1, 32>>>(bsum, nb);
    scanC<<<(NN + 255) / 256, 256>>>(deg, bsum, NN);
    // 9. scatter edges into destination order (packed 16-B records)
    scatter_kernel<<<(2 * E + 255) / 256, 256>>>(
        E, assigns_src, assigns_dst, (const float4*)edge_sat_vc,
        contains_src, contains_dst, (const float4*)edge_sat_cv,
        deg, fill, sedge1, sedge2);

    // 10. Q_c = ctx_emb @ W_c[144:272]  (tiny, SIMT)
    fused_gemm<<<1, 256>>>(C_NU, ctx_emb, W_c + 144 * C_D, Qc);

    // 11. aggregate dir1: var -> clause (writes hc fp16, pre-divided by deg)
    agg_kernel<<<(NC + 7) / 8, 256>>>(
        NC, 0, 0, deg, fill, sedge1, Pv, W_vc, b_vc, hc);
    // 12. aggregate dir2: clause -> var (writes hv fp16)
    agg_kernel<<<(NV + 7) / 8, 256>>>(
        NV, NC, E, deg, fill, sedge2, Pc, W_cv, b_cv, hv);

    // 13. Q_v = ctx_emb @ W_v[144:272]
    fused_gemm<<<1, 256>>>(C_NU, ctx_emb, W_v + 144 * C_D, Qv);

    // 14. new_clause (TF32, fused epilogue) -> out rows [0, NC)
    tc_gemm<<<(NC + 63) / 64, 256, SMEM_TOTAL_TC>>>(
        NC, clause_feats, 16, hc, 1, clause_emb,
        Bc, 272, b_c, Qc, clause_ctx, 1, out, nullptr);
    // 15. new_var (TF32) -> out rows [NC, NC+NV)
    tc_gemm<<<(NV + 63) / 64, 256, SMEM_TOTAL_TC>>>(
        NV, var_feats, 16, hv, 1, var_emb,
        Bv, 272, b_v, Qv, var_ctx, 1, out + (size_t)NC * C_D, nullptr);

    // 16-17. context means over the NEW embeddings
    seg_mean_ctx<<<1024, 128>>>(out, clause_ctx, NC, cacc, ccnt);
    seg_mean_ctx<<<1024, 128>>>(out + (size_t)NC * C_D, var_ctx, NV,
                                cacc + C_NU * C_D, ccnt + C_NU);

    // 18. context update: rows [NC+NV, NC+NV+NU)
    ctx_update<<<C_NU, 128>>>(ctx_feats, ctx_emb, cacc, ccnt, W_u, b_u,
                              out + (size_t)(NC + NV) * C_D);
}

// round 12
// speedup vs baseline: 1.1630x; 1.1630x over previous
#include <cuda_runtime.h>
#include <cuda_fp16.h>
#include <cstdint>

// Problem constants (fixed by the dataset)
#define C_NV 100000
#define C_NC 400000
#define C_NU 64
#define C_E  1200000
#define C_D  128
#define C_NN (C_NC + C_NV)          // concatenated node count for degree/scan

// ---------------- scratch (device globals; no allocation allowed) ----------
__device__ __align__(16) __half g_hc[(size_t)C_NC * C_D];  // clause message means
__device__ __align__(16) __half g_hv[(size_t)C_NV * C_D];  // var message means
__device__ __align__(16) __half g_Pv[(size_t)C_NV * C_D];  // var_emb @ W_vc[4:132]
__device__ __align__(16) __half g_Pc[(size_t)C_NC * C_D];  // clause_emb @ W_cv[4:132]
__device__ float g_Qc[C_NU * C_D];             // ctx_emb @ W_c[144:272]
__device__ float g_Qv[C_NU * C_D];             // ctx_emb @ W_v[144:272]
__device__ float g_ctx_acc[2 * C_NU * C_D];    // [clause sums | var sums]
__device__ float g_ctx_cnt[2 * C_NU];

// CSR edge binning: packed records {src, pad, es01(h2), es23(h2)} = 16 B
__device__ int   g_deg[C_NN];                  // degrees -> exclusive scan (base)
__device__ int   g_fill[C_NN];                 // scatter cursors (== deg after)
__device__ int   g_bsum[256];                  // scan block sums
__device__ __align__(16) uint4 g_sedge1[C_E];  // dir1 (var->clause)
__device__ __align__(16) uint4 g_sedge2[C_E];  // dir2 (clause->var)

// Transposed tf32-rounded weights: layout [n (0..127)][k (0..K-1)], fp32 bits
__device__ __align__(16) float g_Bvc[128 * 128];
__device__ __align__(16) float g_Bcv[128 * 128];
__device__ __align__(16) float g_Bc[128 * 272];
__device__ __align__(16) float g_Bv[128 * 272];

static __device__ __forceinline__ float lrelu(float x) {
    return x >= 0.f ? x : 0.1f * x;
}

static __device__ __forceinline__ uint32_t smem_u32(const void* p) {
    uint32_t a;
    asm("{ .reg .u64 t; cvta.to.shared.u64 t, %1; cvt.u32.u64 %0, t; }"
        : "=r"(a) : "l"(p));
    return a;
}

static __device__ __forceinline__ uint32_t f2tf32(float f) {
    uint32_t u;
    asm("cvt.rna.tf32.f32 %0, %1;" : "=r"(u) : "f"(f));
    return u;
}

#define LDS32(d, addr)                                                         \
    asm volatile("ld.shared.b32 %0, [%1];" : "=r"(d) : "r"(addr))

// mma.sync m16n8k8 tf32 -> fp32
#define MMATF32(c, a, b0, b1)                                                  \
    asm volatile(                                                              \
        "mma.sync.aligned.m16n8k8.row.col.f32.tf32.tf32.f32 "                  \
        "{%0,%1,%2,%3}, {%4,%5,%6,%7}, {%8,%9}, {%0,%1,%2,%3};"                \
        : "+f"((c)[0]), "+f"((c)[1]), "+f"((c)[2]), "+f"((c)[3])               \
        : "r"((a)[0]), "r"((a)[1]), "r"((a)[2]), "r"((a)[3]),                  \
          "r"(b0), "r"(b1))

#define CP_ASYNC16(dst, src, sz)                                               \
    asm volatile("cp.async.cg.shared.global [%0], [%1], 16, %2;"               \
                 :: "r"(dst), "l"(src), "r"(sz))
#define CP_COMMIT() asm volatile("cp.async.commit_group;" ::: "memory")
#define CP_WAIT(n)  asm volatile("cp.async.wait_group %0;" :: "n"(n) : "memory")

// ---------------- zero small accumulators ------------------------------------
__global__ void zero_small(int* deg, int* fill, float* cacc, float* ccnt)
{
    int i = blockIdx.x * blockDim.x + threadIdx.x;
    int stride = gridDim.x * blockDim.x;
    for (int j = i; j < C_NN; j += stride) { deg[j] = 0; fill[j] = 0; }
    for (int j = i; j < 2 * C_NU * C_D; j += stride) cacc[j] = 0.f;
    if (i < 2 * C_NU) ccnt[i] = 0.f;
}

// ---------------- histogram of destinations ---------------------------------
__global__ void hist_kernel(int E, const int* __restrict__ dst1,
                            const int* __restrict__ dst2, int* __restrict__ deg)
{
    int i = blockIdx.x * blockDim.x + threadIdx.x;
    if (i < E)          atomicAdd(&deg[dst1[i]], 1);
    else if (i < 2 * E) atomicAdd(&deg[C_NC + dst2[i - E]], 1);
}

// ---------------- exclusive scan (3 kernels, 4096/block) ---------------------
__global__ void scanA(const int* __restrict__ deg, int n,
                      int* __restrict__ base, int* __restrict__ bsum)
{
    __shared__ int tsum[256];
    const int t = threadIdx.x;
    const int b0 = blockIdx.x * 4096;
    int v[16];
    int s = 0;
#pragma unroll
    for (int j = 0; j < 16; j++) {
        int idx = b0 + t * 16 + j;
        v[j] = (idx < n) ? deg[idx] : 0;
        s += v[j];
    }
    tsum[t] = s;
    __syncthreads();
    for (int off = 1; off < 256; off <<= 1) {
        int u = (t >= off) ? tsum[t - off] : 0;
        __syncthreads();
        tsum[t] += u;
        __syncthreads();
    }
    int run = tsum[t] - s;
#pragma unroll
    for (int j = 0; j < 16; j++) {
        int idx = b0 + t * 16 + j;
        if (idx < n) base[idx] = run;
        run += v[j];
    }
    if (t == 255) bsum[blockIdx.x] = tsum[255];
}

__global__ void scanB(int* bsum, int nb)
{
    if (threadIdx.x == 0 && blockIdx.x == 0) {
        int r = 0;
        for (int i = 0; i < nb; i++) { int d = bsum[i]; bsum[i] = r; r += d; }
    }
}

__global__ void scanC(int* __restrict__ base, const int* __restrict__ bsum, int n)
{
    int i = blockIdx.x * blockDim.x + threadIdx.x;
    if (i < n) base[i] += bsum[i >> 12];
}

// ---------------- scatter edges into destination order ----------------------
__global__ void scatter_kernel(
    int E,
    const int* __restrict__ src1, const int* __restrict__ dst1,
    const float4* __restrict__ es1,
    const int* __restrict__ src2, const int* __restrict__ dst2,
    const float4* __restrict__ es2,
    const int* __restrict__ base, int* __restrict__ fill,
    uint4* __restrict__ sedge1, uint4* __restrict__ sedge2)
{
    int i = blockIdx.x * blockDim.x + threadIdx.x;
    if (i < E) {
        int d = dst1[i];
        int p = base[d] + atomicAdd(&fill[d], 1);
        float4 ev = es1[i];
        __half2 h01 = __floats2half2_rn(ev.x, ev.y);
        __half2 h23 = __floats2half2_rn(ev.z, ev.w);
        uint4 rec;
        rec.x = (uint32_t)src1[i];
        rec.y = 0u;
        rec.z = *reinterpret_cast<uint32_t*>(&h01);
        rec.w = *reinterpret_cast<uint32_t*>(&h23);
        sedge1[p] = rec;
    } else if (i < 2 * E) {
        int e = i - E;
        int d = C_NC + dst2[e];
        int p = base[d] + atomicAdd(&fill[d], 1) - E;
        float4 ev = es2[e];
        __half2 h01 = __floats2half2_rn(ev.x, ev.y);
        __half2 h23 = __floats2half2_rn(ev.z, ev.w);
        uint4 rec;
        rec.x = (uint32_t)src2[e];
        rec.y = 0u;
        rec.z = *reinterpret_cast<uint32_t*>(&h01);
        rec.w = *reinterpret_cast<uint32_t*>(&h23);
        sedge2[p] = rec;
    }
}

// ---------------- CSR aggregate: warp per destination node ------------------
__global__ __launch_bounds__(256) void agg_kernel(
    int N0, int baseoff, int posoff,
    const int* __restrict__ base, const int* __restrict__ fill,
    const uint4* __restrict__ sedge,
    const __half* __restrict__ P,
    const float* __restrict__ W1, const float* __restrict__ b,
    __half* __restrict__ outh)
{
    const int warp = blockIdx.x * 8 + (threadIdx.x >> 5);
    if (warp >= N0) return;
    const int lane = threadIdx.x & 31;
    const int c = lane * 4;

    float w[4][4], bb[4];
#pragma unroll
    for (int r = 0; r < 4; r++)
#pragma unroll
        for (int i = 0; i < 4; i++)
            w[r][i] = W1[r * 128 + c + i];
#pragma unroll
    for (int i = 0; i < 4; i++) bb[i] = b[c + i];

    const int start = base[baseoff + warp] - posoff;
    const int deg   = fill[baseoff + warp];

    float s0 = 0.f, s1 = 0.f, s2 = 0.f, s3 = 0.f;

    auto edge_term = [&](uint4 rec, uint2 praw) {
        float2 e01 = __half22float2(*reinterpret_cast<__half2*>(&rec.z));
        float2 e23 = __half22float2(*reinterpret_cast<__half2*>(&rec.w));
        float2 p01 = __half22float2(*reinterpret_cast<__half2*>(&praw.x));
        float2 p23 = __half22float2(*reinterpret_cast<__half2*>(&praw.y));
        float m0 = bb[0], m1 = bb[1], m2 = bb[2], m3 = bb[3];
        m0 = fmaf(e01.x, w[0][0], m0); m0 = fmaf(e01.y, w[1][0], m0);
        m0 = fmaf(e23.x, w[2][0], m0); m0 = fmaf(e23.y, w[3][0], m0);
        m1 = fmaf(e01.x, w[0][1], m1); m1 = fmaf(e01.y, w[1][1], m1);
        m1 = fmaf(e23.x, w[2][1], m1); m1 = fmaf(e23.y, w[3][1], m1);
        m2 = fmaf(e01.x, w[0][2], m2); m2 = fmaf(e01.y, w[1][2], m2);
        m2 = fmaf(e23.x, w[2][2], m2); m2 = fmaf(e23.y, w[3][2], m2);
        m3 = fmaf(e01.x, w[0][3], m3); m3 = fmaf(e01.y, w[1][3], m3);
        m3 = fmaf(e23.x, w[2][3], m3); m3 = fmaf(e23.y, w[3][3], m3);
        s0 += lrelu(m0 + p01.x);
        s1 += lrelu(m1 + p01.y);
        s2 += lrelu(m2 + p23.x);
        s3 += lrelu(m3 + p23.y);
    };

    int j = 0;
    for (; j + 4 <= deg; j += 4) {
        uint4 r0 = sedge[start + j + 0];
        uint4 r1 = sedge[start + j + 1];
        uint4 r2 = sedge[start + j + 2];
        uint4 r3 = sedge[start + j + 3];
        uint2 q0 = *(const uint2*)(P + (size_t)r0.x * 128 + c);
        uint2 q1 = *(const uint2*)(P + (size_t)r1.x * 128 + c);
        uint2 q2 = *(const uint2*)(P + (size_t)r2.x * 128 + c);
        uint2 q3 = *(const uint2*)(P + (size_t)r3.x * 128 + c);
        edge_term(r0, q0);
        edge_term(r1, q1);
        edge_term(r2, q2);
        edge_term(r3, q3);
    }
    for (; j < deg; j++) {
        uint4 r0 = sedge[start + j];
        uint2 q0 = *(const uint2*)(P + (size_t)r0.x * 128 + c);
        edge_term(r0, q0);
    }

    float inv = (deg > 0) ? (1.f / (float)deg) : 0.f;
    __half2 o01 = __floats2half2_rn(s0 * inv, s1 * inv);
    __half2 o23 = __floats2half2_rn(s2 * inv, s3 * inv);
    uint2 pk;
    pk.x = *reinterpret_cast<uint32_t*>(&o01);
    pk.y = *reinterpret_cast<uint32_t*>(&o23);
    *(uint2*)(outh + (size_t)warp * 128 + c) = pk;
}

// ---------------- weight transpose + tf32 rounding --------------------------
__global__ void wprep(const float* __restrict__ Wvc, const float* __restrict__ Wcv,
                      const float* __restrict__ Wc,  const float* __restrict__ Wv)
{
    int i = blockIdx.x * blockDim.x + threadIdx.x;
    if (i >= 102400) return;
    float w;
    float* dst;
    int di;
    if (i < 16384) {                       // vc: K=128, W rows 4..131
        int n = i >> 7, k = i & 127;
        w = Wvc[(4 + k) * 128 + n];
        dst = g_Bvc; di = n * 128 + k;
    } else if (i < 32768) {                // cv: K=128, W rows 4..131
        int j = i - 16384;
        int n = j >> 7, k = j & 127;
        w = Wcv[(4 + k) * 128 + n];
        dst = g_Bcv; di = n * 128 + k;
    } else if (i < 67584) {                // c: K=272, W rows {0..143, 272..399}
        int j = i - 32768;
        int n = j / 272, k = j % 272;
        int kk = (k < 144) ? k : k + 128;
        w = Wc[kk * 128 + n];
        dst = g_Bc; di = n * 272 + k;
    } else {                               // v: K=272
        int j = i - 67584;
        int n = j / 272, k = j % 272;
        int kk = (k < 144) ? k : k + 128;
        w = Wv[kk * 128 + n];
        dst = g_Bv; di = n * 272 + k;
    }
    uint32_t t = f2tf32(w);
    dst[di] = __uint_as_float(t);
}

// ---------------- TF32 GEMM (R10-proven: BM=64 x BN=128, 3 CTAs/SM) ---------
// out[row,:] = act([Af | Ah | Ae] @ B^T + bias + Q[qidx[row]])
// A: LDG 1-ahead reg-prefetch -> cvt.rna.tf32 -> 2-buffer smem [64][36].
// B: cp.async 1-ahead -> 3-stage ring [128][36].
#define BK 32
#define AST 36
#define A_BUF (64 * AST * 4)               // 9216 B
#define B_STG (128 * AST * 4)              // 18432 B
#define B_BASE (2 * A_BUF)                 // 18432
#define SMEM_TOTAL_TC (B_BASE + 3 * B_STG) // 73728

__global__ __launch_bounds__(256, 3) void tc_gemm(
    int M,
    const float* __restrict__ Af, int KF,
    const void* __restrict__ Ah, int ah_half,
    const float* __restrict__ Ae,
    const float* __restrict__ Bt,          // [128][Ktot] tf32 bits
    int Ktot,
    const float* __restrict__ bias, const float* __restrict__ Q,
    const int* __restrict__ qidx, int act,
    float* __restrict__ out, __half* __restrict__ out16)
{
    extern __shared__ char smem[];
    const uint32_t sb = smem_u32(smem);
    const int tid  = threadIdx.x;
    const int wid  = tid >> 5;
    const int lane = tid & 31;

    const int row0 = blockIdx.x * 64;

    // A staging assignment: row r (0..63), 8-col quad q
    const int r = tid >> 2;
    const int q = (tid & 3) * 8;
    int grow = row0 + r;
    if (grow >= M) grow = M - 1;

    // B cp.async assignment: row brow (0..127), 16-float half bh
    const int brow = tid >> 1;
    const int bhf  = (tid & 1) * 16;
    const float* b_row = Bt + (size_t)brow * Ktot;

    const int nchunks = (Ktot + BK - 1) / BK;

    auto stage_b = [&](int c) {
        int s = c % 3;
        uint32_t dbase = sb + B_BASE + (uint32_t)s * B_STG +
                         (uint32_t)(brow * AST) * 4;
#pragma unroll
        for (int j2 = 0; j2 < 4; j2++) {
            int bq = bhf + j2 * 4;            // float offset within chunk
            int gk = c * BK + bq;
            int rem = Ktot - gk;
            int sz = rem >= 4 ? 16 : 0;       // Ktot multiple of 16
            int gks = (rem >= 4) ? gk : (Ktot - 4);
            CP_ASYNC16(dbase + (uint32_t)bq * 4, b_row + gks, sz);
        }
    };

    auto load_a = [&](int c, float4* va) {
        int k0 = c * BK;
#pragma unroll
        for (int j = 0; j < 2; j++) {
            int gk = k0 + q + j * 4;
            float4 v = make_float4(0.f, 0.f, 0.f, 0.f);
            if (gk < KF) {
                v = *(const float4*)(Af + (size_t)grow * KF + gk);
            } else if (gk < KF + 128) {
                if (ah_half) {
                    uint2 raw = *(const uint2*)((const __half*)Ah +
                                                (size_t)grow * 128 + (gk - KF));
                    float2 a01 = __half22float2(*reinterpret_cast<__half2*>(&raw.x));
                    float2 a23 = __half22float2(*reinterpret_cast<__half2*>(&raw.y));
                    v = make_float4(a01.x, a01.y, a23.x, a23.y);
                } else {
                    v = *(const float4*)((const float*)Ah +
                                         (size_t)grow * 128 + (gk - KF));
                }
            } else if (gk < Ktot) {
                v = *(const float4*)(Ae + (size_t)grow * 128 + (gk - KF - 128));
            }
            va[j] = v;
        }
    };

    // warp tile: 32(m) x 32(n); warps 2(m) x 4(n)
    const int m_base = (wid & 1) * 32;
    const int n_base = (wid >> 1) * 32;
    float acc[2][4][4];
#pragma unroll
    for (int mt = 0; mt < 2; mt++)
#pragma unroll
        for (int nt = 0; nt < 4; nt++)
            acc[mt][nt][0] = acc[mt][nt][1] = acc[mt][nt][2] = acc[mt][nt][3] = 0.f;

    const int gr = lane >> 2;     // 0..7
    const int tc = lane & 3;      // 0..3

    // ---- prologue ----
    stage_b(0); CP_COMMIT();
    float4 va[2];
    load_a(0, va);

    for (int c = 0; c < nchunks; c++) {
        const int abuf = c & 1;
        const uint32_t a_base = sb + (uint32_t)abuf * A_BUF;

        // cvt + store staged A chunk: 2 x uint4 at [r][q..q+7]
#pragma unroll
        for (int j = 0; j < 2; j++) {
            uint4 t;
            t.x = f2tf32(va[j].x);
            t.y = f2tf32(va[j].y);
            t.z = f2tf32(va[j].z);
            t.w = f2tf32(va[j].w);
            *(uint4*)(smem + (a_base - sb) +
                      (uint32_t)(r * AST + q + j * 4) * 4) = t;
        }

        if (c + 1 < nchunks) {
            stage_b(c + 1); CP_COMMIT();
            load_a(c + 1, va);
            CP_WAIT(1);
        } else {
            CP_WAIT(0);
        }
        __syncthreads();

        const uint32_t b_base = sb + B_BASE + (uint32_t)(c % 3) * B_STG;

#pragma unroll
        for (int ks = 0; ks < 4; ks++) {
            const int k = ks * 8;
            uint32_t af[2][4];
#pragma unroll
            for (int mt = 0; mt < 2; mt++) {
                uint32_t r0 = a_base +
                    (uint32_t)((m_base + mt * 16 + gr) * AST + k + tc) * 4;
                uint32_t r1 = r0 + (uint32_t)(8 * AST) * 4;
                LDS32(af[mt][0], r0);
                LDS32(af[mt][1], r1);
                LDS32(af[mt][2], r0 + 16);
                LDS32(af[mt][3], r1 + 16);
            }
            uint32_t bf[4][2];
#pragma unroll
            for (int nt = 0; nt < 4; nt++) {
                uint32_t b0 = b_base +
                    (uint32_t)((n_base + nt * 8 + gr) * AST + k + tc) * 4;
                LDS32(bf[nt][0], b0);
                LDS32(bf[nt][1], b0 + 16);
            }
#pragma unroll
            for (int mt = 0; mt < 2; mt++)
#pragma unroll
                for (int nt = 0; nt < 4; nt++)
                    MMATF32(acc[mt][nt], af[mt], bf[nt][0], bf[nt][1]);
        }
        // A double-buffer + B 3-stage ring: no second barrier needed.
    }

    // ---- epilogue ----
#pragma unroll
    for (int mt = 0; mt < 2; mt++) {
        int row_a = row0 + m_base + mt * 16 + gr;
        int row_b = row_a + 8;
        const float* qa = nullptr;
        const float* qb = nullptr;
        if (Q) {
            if (row_a < M) qa = Q + (size_t)qidx[row_a] * 128;
            if (row_b < M) qb = Q + (size_t)qidx[row_b] * 128;
        }
#pragma unroll
        for (int nt = 0; nt < 4; nt++) {
            int col = n_base + nt * 8 + tc * 2;
            float b0 = 0.f, b1 = 0.f;
            if (bias) { b0 = bias[col]; b1 = bias[col + 1]; }
            if (row_a < M) {
                float v0 = acc[mt][nt][0] + b0;
                float v1 = acc[mt][nt][1] + b1;
                if (qa) { v0 += qa[col]; v1 += qa[col + 1]; }
                if (act) { v0 = lrelu(v0); v1 = lrelu(v1); }
                if (out16) {
                    *(__half2*)(out16 + (size_t)row_a * 128 + col) =
                        __floats2half2_rn(v0, v1);
                } else {
                    *(float2*)(out + (size_t)row_a * 128 + col) =
                        make_float2(v0, v1);
                }
            }
            if (row_b < M) {
                float v0 = acc[mt][nt][2] + b0;
                float v1 = acc[mt][nt][3] + b1;
                if (qb) { v0 += qb[col]; v1 += qb[col + 1]; }
                if (act) { v0 = lrelu(v0); v1 = lrelu(v1); }
                if (out16) {
                    *(__half2*)(out16 + (size_t)row_b * 128 + col) =
                        __floats2half2_rn(v0, v1);
                } else {
                    *(float2*)(out + (size_t)row_b * 128 + col) =
                        make_float2(v0, v1);
                }
            }
        }
    }
}

// ---------------- small SIMT GEMM (tiny Q precomputes, M=64,K=128) ----------
__global__ __launch_bounds__(256, 2) void fused_gemm(
    int M,
    const float* __restrict__ Ah, const float* __restrict__ Wh,
    float* __restrict__ out)
{
    __shared__ float As[64][16];
    __shared__ float Ws[16][128];

    const int t  = threadIdx.x;
    const int tx = t & 31;
    const int ty = t >> 5;
    const int row0 = blockIdx.x * 64;

    float acc[8][4];
#pragma unroll
    for (int r = 0; r < 8; r++)
        acc[r][0] = acc[r][1] = acc[r][2] = acc[r][3] = 0.f;

    const int aRow = t >> 2;
    const int aK   = (t & 3) * 4;
    const int wK   = t >> 4;
    const int wC   = (t & 15) * 8;

    int arow_g = row0 + aRow;
    if (arow_g >= M) arow_g = M - 1;

    for (int kk = 0; kk < 128; kk += 16) {
        __syncthreads();
        float4 av = *(const float4*)(Ah + (size_t)arow_g * 128 + kk + aK);
        *(float4*)&As[aRow][aK] = av;
        const float* wp = Wh + (size_t)(kk + wK) * 128 + wC;
        *(float4*)&Ws[wK][wC]     = *(const float4*)(wp);
        *(float4*)&Ws[wK][wC + 4] = *(const float4*)(wp + 4);
        __syncthreads();

#pragma unroll
        for (int k = 0; k < 16; k++) {
            float4 w = *(const float4*)&Ws[k][tx * 4];
#pragma unroll
            for (int r = 0; r < 8; r++) {
                float a = As[ty * 8 + r][k];
                acc[r][0] = fmaf(a, w.x, acc[r][0]);
                acc[r][1] = fmaf(a, w.y, acc[r][1]);
                acc[r][2] = fmaf(a, w.z, acc[r][2]);
                acc[r][3] = fmaf(a, w.w, acc[r][3]);
            }
        }
    }

#pragma unroll
    for (int r = 0; r < 8; r++) {
        int row = row0 + ty * 8 + r;
        if (row < M) {
            float4 v = make_float4(acc[r][0], acc[r][1], acc[r][2], acc[r][3]);
            *(float4*)(out + (size_t)row * 128 + tx * 4) = v;
        }
    }
}

// ---------------- segment mean into NU=64 contexts --------------------------
__global__ __launch_bounds__(128) void seg_mean_ctx(
    const float* __restrict__ srcm, const int* __restrict__ ids, int n,
    float* __restrict__ acc, float* __restrict__ cntp)
{
    __shared__ float sacc[64 * 128];
    __shared__ float scnt[64];
    const int t = threadIdx.x;
    for (int i = t; i < 64 * 128; i += 128) sacc[i] = 0.f;
    if (t < 64) scnt[t] = 0.f;
    __syncthreads();

    for (long r0 = (long)blockIdx.x * 8; r0 < n; r0 += (long)gridDim.x * 8) {
        float v[8]; int id[8]; int k = 0;
#pragma unroll
        for (int u = 0; u < 8; u++) {
            long r = r0 + u;
            if (r < n) {
                id[k] = ids[r];
                v[k]  = srcm[(size_t)r * 128 + t];
                k++;
            }
        }
        for (int u = 0; u < k; u++) {
            sacc[id[u] * 128 + t] += v[u];
            if (t == 0) scnt[id[u]] += 1.f;
        }
    }
    __syncthreads();
    for (int i = t; i < 64 * 128; i += 128) atomicAdd(&acc[i], sacc[i]);
    if (t < 64) atomicAdd(&cntp[t], scnt[t]);
}

// ---------------- context update (64 rows, K=400) ---------------------------
__global__ __launch_bounds__(128) void ctx_update(
    const float* __restrict__ ctx_feats,
    const float* __restrict__ ctx_emb,
    const float* __restrict__ acc,
    const float* __restrict__ cntp,
    const float* __restrict__ Wu,
    const float* __restrict__ bu,
    float* __restrict__ out)
{
    const int u = blockIdx.x;
    const int t = threadIdx.x;
    __shared__ float a[400];

    if (t < 16) a[t] = ctx_feats[u * 16 + t];
    float cc = fmaxf(cntp[u], 1.f);
    float cv = fmaxf(cntp[64 + u], 1.f);
    a[16 + t]  = acc[u * 128 + t] / cc;
    a[144 + t] = acc[64 * 128 + u * 128 + t] / cv;
    a[272 + t] = ctx_emb[u * 128 + t];
    __syncthreads();

    float s = bu[t];
    for (int k = 0; k < 400; k++) s = fmaf(a[k], Wu[k * 128 + t], s);
    out[(size_t)u * 128 + t] = lrelu(s);
}

// ---------------- launch ----------------------------------------------------
extern "C" void kernel_launch(void* const* d_in, const int* in_sizes, int n_in,
                              void* d_out, int out_size)
{
    const float* var_emb      = (const float*)d_in[0];
    const float* clause_emb   = (const float*)d_in[1];
    const float* ctx_emb      = (const float*)d_in[2];
    const float* var_feats    = (const float*)d_in[3];
    const float* clause_feats = (const float*)d_in[4];
    const float* ctx_feats    = (const float*)d_in[5];
    const float* edge_sat_vc  = (const float*)d_in[6];
    const float* edge_sat_cv  = (const float*)d_in[7];
    const float* W_vc         = (const float*)d_in[8];
    const float* b_vc         = (const float*)d_in[9];
    const float* W_cv         = (const float*)d_in[10];
    const float* b_cv         = (const float*)d_in[11];
    const float* W_c          = (const float*)d_in[12];
    const float* b_c          = (const float*)d_in[13];
    const float* W_v          = (const float*)d_in[14];
    const float* b_v          = (const float*)d_in[15];
    const float* W_u          = (const float*)d_in[16];
    const float* b_u          = (const float*)d_in[17];
    const int* assigns_src    = (const int*)d_in[18];
    const int* assigns_dst    = (const int*)d_in[19];
    const int* contains_src   = (const int*)d_in[20];
    const int* contains_dst   = (const int*)d_in[21];
    const int* var_ctx        = (const int*)d_in[22];
    const int* clause_ctx     = (const int*)d_in[23];

    const int NV = in_sizes[0] / C_D;
    const int NC = in_sizes[1] / C_D;
    const int E  = in_sizes[18];
    const int NN = NC + NV;

    float *Qc, *Qv, *cacc, *ccnt;
    __half *Pv, *Pc, *hc, *hv;
    cudaGetSymbolAddress((void**)&hc,   g_hc);
    cudaGetSymbolAddress((void**)&hv,   g_hv);
    cudaGetSymbolAddress((void**)&Pv,   g_Pv);
    cudaGetSymbolAddress((void**)&Pc,   g_Pc);
    cudaGetSymbolAddress((void**)&Qc,   g_Qc);
    cudaGetSymbolAddress((void**)&Qv,   g_Qv);
    cudaGetSymbolAddress((void**)&cacc, g_ctx_acc);
    cudaGetSymbolAddress((void**)&ccnt, g_ctx_cnt);

    int *deg, *fill, *bsum;
    uint4 *sedge1, *sedge2;
    cudaGetSymbolAddress((void**)&deg,    g_deg);
    cudaGetSymbolAddress((void**)&fill,   g_fill);
    cudaGetSymbolAddress((void**)&bsum,   g_bsum);
    cudaGetSymbolAddress((void**)&sedge1, g_sedge1);
    cudaGetSymbolAddress((void**)&sedge2, g_sedge2);

    float *Bvc, *Bcv, *Bc, *Bv;
    cudaGetSymbolAddress((void**)&Bvc, g_Bvc);
    cudaGetSymbolAddress((void**)&Bcv, g_Bcv);
    cudaGetSymbolAddress((void**)&Bc,  g_Bc);
    cudaGetSymbolAddress((void**)&Bv,  g_Bv);

    float* out = (float*)d_out;

    cudaFuncSetAttribute(tc_gemm, cudaFuncAttributeMaxDynamicSharedMemorySize,
                         SMEM_TOTAL_TC);

    const int nb = (NN + 4095) / 4096;   // scan blocks

    // 1. zero small accumulators (deg, fill, ctx)
    zero_small<<<512, 256>>>(deg, fill, cacc, ccnt);
    // 2. weight transpose + tf32 rounding
    wprep<<<(102400 + 255) / 256, 256>>>(W_vc, W_cv, W_c, W_v);
    // 3. P_v = var_emb @ W_vc[4:132]   (TF32, fp16 out)
    tc_gemm<<<(NV + 63) / 64, 256, SMEM_TOTAL_TC>>>(
        NV, nullptr, 0, var_emb, 0, nullptr,
        Bvc, 128, nullptr, nullptr, nullptr, 0, nullptr, Pv);
    // 4. P_c = clause_emb @ W_cv[4:132] (TF32, fp16 out) <-- ncu control point
    tc_gemm<<<(NC + 63) / 64, 256, SMEM_TOTAL_TC>>>(
        NC, nullptr, 0, clause_emb, 0, nullptr,
        Bcv, 128, nullptr, nullptr, nullptr, 0, nullptr, Pc);

    // 5. degree histogram (both directions)
    hist_kernel<<<(2 * E + 255) / 256, 256>>>(E, assigns_dst, contains_dst, deg);
    // 6-8. exclusive scan deg -> base (in place)
    scanA<<<nb, 256>>>(deg, NN, deg, bsum);
    scanB<<<1, 32>>>(bsum, nb);
    scanC<<<(NN + 255) / 256, 256>>>(deg, bsum, NN);
    // 9. scatter edges into destination order (packed 16-B records)
    scatter_kernel<<<(2 * E + 255) / 256, 256>>>(
        E, assigns_src, assigns_dst, (const float4*)edge_sat_vc,
        contains_src, contains_dst, (const float4*)edge_sat_cv,
        deg, fill, sedge1, sedge2);

    // 10. Q_c = ctx_emb @ W_c[144:272]  (tiny, SIMT)
    fused_gemm<<<1, 256>>>(C_NU, ctx_emb, W_c + 144 * C_D, Qc);

    // 11. aggregate dir1: var -> clause (writes hc fp16, pre-divided by deg)
    agg_kernel<<<(NC + 7) / 8, 256>>>(
        NC, 0, 0, deg, fill, sedge1, Pv, W_vc, b_vc, hc);
    // 12. aggregate dir2: clause -> var (writes hv fp16)
    agg_kernel<<<(NV + 7) / 8, 256>>>(
        NV, NC, E, deg, fill, sedge2, Pc, W_cv, b_cv, hv);

    // 13. Q_v = ctx_emb @ W_v[144:272]
    fused_gemm<<<1, 256>>>(C_NU, ctx_emb, W_v + 144 * C_D, Qv);

    // 14. new_clause (TF32, fused epilogue) -> out rows [0, NC)
    tc_gemm<<<(NC + 63) / 64, 256, SMEM_TOTAL_TC>>>(
        NC, clause_feats, 16, hc, 1, clause_emb,
        Bc, 272, b_c, Qc, clause_ctx, 1, out, nullptr);
    // 15. new_var (TF32) -> out rows [NC, NC+NV)
    tc_gemm<<<(NV + 63) / 64, 256, SMEM_TOTAL_TC>>>(
        NV, var_feats, 16, hv, 1, var_emb,
        Bv, 272, b_v, Qv, var_ctx, 1, out + (size_t)NC * C_D, nullptr);

    // 16-17. context means over the NEW embeddings
    seg_mean_ctx<<<2048, 128>>>(out, clause_ctx, NC, cacc, ccnt);
    seg_mean_ctx<<<2048, 128>>>(out + (size_t)NC * C_D, var_ctx, NV,
                                cacc + C_NU * C_D, ccnt + C_NU);

    // 18. context update: rows [NC+NV, NC+NV+NU)
    ctx_update<<<C_NU, 128>>>(ctx_feats, ctx_emb, cacc, ccnt, W_u, b_u,
                              out + (size_t)(NC + NV) * C_D);
}

// round 13
// speedup vs baseline: 1.2310x; 1.0585x over previous
#include <cuda_runtime.h>
#include <cuda_fp16.h>
#include <cstdint>

// Problem constants (fixed by the dataset)
#define C_NV 100000
#define C_NC 400000
#define C_NU 64
#define C_E  1200000
#define C_D  128
#define C_NN (C_NC + C_NV)          // concatenated node count for degree/scan

// ---------------- scratch (device globals; no allocation allowed) ----------
__device__ __align__(16) __half g_hc[(size_t)C_NC * C_D];  // clause message means
__device__ __align__(16) __half g_hv[(size_t)C_NV * C_D];  // var message means
__device__ __align__(16) __half g_Pv[(size_t)C_NV * C_D];  // var_emb @ W_vc[4:132]
__device__ __align__(16) __half g_Pc[(size_t)C_NC * C_D];  // clause_emb @ W_cv[4:132]
__device__ float g_Qc[C_NU * C_D];             // ctx_emb @ W_c[144:272]
__device__ float g_Qv[C_NU * C_D];             // ctx_emb @ W_v[144:272]
__device__ float g_ctx_acc[2 * C_NU * C_D];    // [clause sums | var sums]
__device__ float g_ctx_cnt[2 * C_NU];

// CSR edge binning: packed records {src, pad, es01(h2), es23(h2)} = 16 B
__device__ int   g_deg[C_NN];                  // degrees -> exclusive scan (base)
__device__ int   g_fill[C_NN];                 // scatter cursors (== deg after)
__device__ int   g_bsum[256];                  // scan block sums
__device__ __align__(16) uint4 g_sedge1[C_E];  // dir1 (var->clause)
__device__ __align__(16) uint4 g_sedge2[C_E];  // dir2 (clause->var)

// Transposed tf32-rounded weights: layout [n (0..127)][k (0..K-1)], fp32 bits
__device__ __align__(16) float g_Bvc[128 * 128];
__device__ __align__(16) float g_Bcv[128 * 128];
__device__ __align__(16) float g_Bc[128 * 272];
__device__ __align__(16) float g_Bv[128 * 272];

static __device__ __forceinline__ float lrelu(float x) {
    return x >= 0.f ? x : 0.1f * x;
}

static __device__ __forceinline__ uint32_t smem_u32(const void* p) {
    uint32_t a;
    asm("{ .reg .u64 t; cvta.to.shared.u64 t, %1; cvt.u32.u64 %0, t; }"
        : "=r"(a) : "l"(p));
    return a;
}

static __device__ __forceinline__ uint32_t f2tf32(float f) {
    uint32_t u;
    asm("cvt.rna.tf32.f32 %0, %1;" : "=r"(u) : "f"(f));
    return u;
}

#define LDS32(d, addr)                                                         \
    asm volatile("ld.shared.b32 %0, [%1];" : "=r"(d) : "r"(addr))

// mma.sync m16n8k8 tf32 -> fp32
#define MMATF32(c, a, b0, b1)                                                  \
    asm volatile(                                                              \
        "mma.sync.aligned.m16n8k8.row.col.f32.tf32.tf32.f32 "                  \
        "{%0,%1,%2,%3}, {%4,%5,%6,%7}, {%8,%9}, {%0,%1,%2,%3};"                \
        : "+f"((c)[0]), "+f"((c)[1]), "+f"((c)[2]), "+f"((c)[3])               \
        : "r"((a)[0]), "r"((a)[1]), "r"((a)[2]), "r"((a)[3]),                  \
          "r"(b0), "r"(b1))

#define CP_ASYNC16(dst, src, sz)                                               \
    asm volatile("cp.async.cg.shared.global [%0], [%1], 16, %2;"               \
                 :: "r"(dst), "l"(src), "r"(sz))
#define CP_COMMIT() asm volatile("cp.async.commit_group;" ::: "memory")
#define CP_WAIT(n)  asm volatile("cp.async.wait_group %0;" :: "n"(n) : "memory")

// ---------------- zero small accumulators ------------------------------------
__global__ void zero_small(int* deg, int* fill, float* cacc, float* ccnt)
{
    int i = blockIdx.x * blockDim.x + threadIdx.x;
    int stride = gridDim.x * blockDim.x;
    for (int j = i; j < C_NN; j += stride) { deg[j] = 0; fill[j] = 0; }
    for (int j = i; j < 2 * C_NU * C_D; j += stride) cacc[j] = 0.f;
    if (i < 2 * C_NU) ccnt[i] = 0.f;
}

// ---------------- histogram of destinations ---------------------------------
__global__ void hist_kernel(int E, const int* __restrict__ dst1,
                            const int* __restrict__ dst2, int* __restrict__ deg)
{
    int i = blockIdx.x * blockDim.x + threadIdx.x;
    if (i < E)          atomicAdd(&deg[dst1[i]], 1);
    else if (i < 2 * E) atomicAdd(&deg[C_NC + dst2[i - E]], 1);
}

// ---------------- exclusive scan (3 kernels, 4096/block) ---------------------
__global__ void scanA(const int* __restrict__ deg, int n,
                      int* __restrict__ base, int* __restrict__ bsum)
{
    __shared__ int tsum[256];
    const int t = threadIdx.x;
    const int b0 = blockIdx.x * 4096;
    int v[16];
    int s = 0;
#pragma unroll
    for (int j = 0; j < 16; j++) {
        int idx = b0 + t * 16 + j;
        v[j] = (idx < n) ? deg[idx] : 0;
        s += v[j];
    }
    tsum[t] = s;
    __syncthreads();
    for (int off = 1; off < 256; off <<= 1) {
        int u = (t >= off) ? tsum[t - off] : 0;
        __syncthreads();
        tsum[t] += u;
        __syncthreads();
    }
    int run = tsum[t] - s;
#pragma unroll
    for (int j = 0; j < 16; j++) {
        int idx = b0 + t * 16 + j;
        if (idx < n) base[idx] = run;
        run += v[j];
    }
    if (t == 255) bsum[blockIdx.x] = tsum[255];
}

__global__ void scanB(int* bsum, int nb)
{
    if (threadIdx.x == 0 && blockIdx.x == 0) {
        int r = 0;
        for (int i = 0; i < nb; i++) { int d = bsum[i]; bsum[i] = r; r += d; }
    }
}

__global__ void scanC(int* __restrict__ base, const int* __restrict__ bsum, int n)
{
    int i = blockIdx.x * blockDim.x + threadIdx.x;
    if (i < n) base[i] += bsum[i >> 12];
}

// ---------------- scatter edges into destination order ----------------------
__global__ void scatter_kernel(
    int E,
    const int* __restrict__ src1, const int* __restrict__ dst1,
    const float4* __restrict__ es1,
    const int* __restrict__ src2, const int* __restrict__ dst2,
    const float4* __restrict__ es2,
    const int* __restrict__ base, int* __restrict__ fill,
    uint4* __restrict__ sedge1, uint4* __restrict__ sedge2)
{
    int i = blockIdx.x * blockDim.x + threadIdx.x;
    if (i < E) {
        int d = dst1[i];
        int p = base[d] + atomicAdd(&fill[d], 1);
        float4 ev = es1[i];
        __half2 h01 = __floats2half2_rn(ev.x, ev.y);
        __half2 h23 = __floats2half2_rn(ev.z, ev.w);
        uint4 rec;
        rec.x = (uint32_t)src1[i];
        rec.y = 0u;
        rec.z = *reinterpret_cast<uint32_t*>(&h01);
        rec.w = *reinterpret_cast<uint32_t*>(&h23);
        sedge1[p] = rec;
    } else if (i < 2 * E) {
        int e = i - E;
        int d = C_NC + dst2[e];
        int p = base[d] + atomicAdd(&fill[d], 1) - E;
        float4 ev = es2[e];
        __half2 h01 = __floats2half2_rn(ev.x, ev.y);
        __half2 h23 = __floats2half2_rn(ev.z, ev.w);
        uint4 rec;
        rec.x = (uint32_t)src2[e];
        rec.y = 0u;
        rec.z = *reinterpret_cast<uint32_t*>(&h01);
        rec.w = *reinterpret_cast<uint32_t*>(&h23);
        sedge2[p] = rec;
    }
}

// ---------------- CSR aggregate: warp per destination node ------------------
__global__ __launch_bounds__(256) void agg_kernel(
    int N0, int baseoff, int posoff,
    const int* __restrict__ base, const int* __restrict__ fill,
    const uint4* __restrict__ sedge,
    const __half* __restrict__ P,
    const float* __restrict__ W1, const float* __restrict__ b,
    __half* __restrict__ outh)
{
    const int warp = blockIdx.x * 8 + (threadIdx.x >> 5);
    if (warp >= N0) return;
    const int lane = threadIdx.x & 31;
    const int c = lane * 4;

    float w[4][4], bb[4];
#pragma unroll
    for (int r = 0; r < 4; r++)
#pragma unroll
        for (int i = 0; i < 4; i++)
            w[r][i] = W1[r * 128 + c + i];
#pragma unroll
    for (int i = 0; i < 4; i++) bb[i] = b[c + i];

    const int start = base[baseoff + warp] - posoff;
    const int deg   = fill[baseoff + warp];

    float s0 = 0.f, s1 = 0.f, s2 = 0.f, s3 = 0.f;

    auto edge_term = [&](uint4 rec, uint2 praw) {
        float2 e01 = __half22float2(*reinterpret_cast<__half2*>(&rec.z));
        float2 e23 = __half22float2(*reinterpret_cast<__half2*>(&rec.w));
        float2 p01 = __half22float2(*reinterpret_cast<__half2*>(&praw.x));
        float2 p23 = __half22float2(*reinterpret_cast<__half2*>(&praw.y));
        float m0 = bb[0], m1 = bb[1], m2 = bb[2], m3 = bb[3];
        m0 = fmaf(e01.x, w[0][0], m0); m0 = fmaf(e01.y, w[1][0], m0);
        m0 = fmaf(e23.x, w[2][0], m0); m0 = fmaf(e23.y, w[3][0], m0);
        m1 = fmaf(e01.x, w[0][1], m1); m1 = fmaf(e01.y, w[1][1], m1);
        m1 = fmaf(e23.x, w[2][1], m1); m1 = fmaf(e23.y, w[3][1], m1);
        m2 = fmaf(e01.x, w[0][2], m2); m2 = fmaf(e01.y, w[1][2], m2);
        m2 = fmaf(e23.x, w[2][2], m2); m2 = fmaf(e23.y, w[3][2], m2);
        m3 = fmaf(e01.x, w[0][3], m3); m3 = fmaf(e01.y, w[1][3], m3);
        m3 = fmaf(e23.x, w[2][3], m3); m3 = fmaf(e23.y, w[3][3], m3);
        s0 += lrelu(m0 + p01.x);
        s1 += lrelu(m1 + p01.y);
        s2 += lrelu(m2 + p23.x);
        s3 += lrelu(m3 + p23.y);
    };

    int j = 0;
    for (; j + 4 <= deg; j += 4) {
        uint4 r0 = sedge[start + j + 0];
        uint4 r1 = sedge[start + j + 1];
        uint4 r2 = sedge[start + j + 2];
        uint4 r3 = sedge[start + j + 3];
        uint2 q0 = *(const uint2*)(P + (size_t)r0.x * 128 + c);
        uint2 q1 = *(const uint2*)(P + (size_t)r1.x * 128 + c);
        uint2 q2 = *(const uint2*)(P + (size_t)r2.x * 128 + c);
        uint2 q3 = *(const uint2*)(P + (size_t)r3.x * 128 + c);
        edge_term(r0, q0);
        edge_term(r1, q1);
        edge_term(r2, q2);
        edge_term(r3, q3);
    }
    for (; j < deg; j++) {
        uint4 r0 = sedge[start + j];
        uint2 q0 = *(const uint2*)(P + (size_t)r0.x * 128 + c);
        edge_term(r0, q0);
    }

    float inv = (deg > 0) ? (1.f / (float)deg) : 0.f;
    __half2 o01 = __floats2half2_rn(s0 * inv, s1 * inv);
    __half2 o23 = __floats2half2_rn(s2 * inv, s3 * inv);
    uint2 pk;
    pk.x = *reinterpret_cast<uint32_t*>(&o01);
    pk.y = *reinterpret_cast<uint32_t*>(&o23);
    *(uint2*)(outh + (size_t)warp * 128 + c) = pk;
}

// ---------------- weight transpose + tf32 rounding --------------------------
__global__ void wprep(const float* __restrict__ Wvc, const float* __restrict__ Wcv,
                      const float* __restrict__ Wc,  const float* __restrict__ Wv)
{
    int i = blockIdx.x * blockDim.x + threadIdx.x;
    if (i >= 102400) return;
    float w;
    float* dst;
    int di;
    if (i < 16384) {                       // vc: K=128, W rows 4..131
        int n = i >> 7, k = i & 127;
        w = Wvc[(4 + k) * 128 + n];
        dst = g_Bvc; di = n * 128 + k;
    } else if (i < 32768) {                // cv: K=128, W rows 4..131
        int j = i - 16384;
        int n = j >> 7, k = j & 127;
        w = Wcv[(4 + k) * 128 + n];
        dst = g_Bcv; di = n * 128 + k;
    } else if (i < 67584) {                // c: K=272, W rows {0..143, 272..399}
        int j = i - 32768;
        int n = j / 272, k = j % 272;
        int kk = (k < 144) ? k : k + 128;
        w = Wc[kk * 128 + n];
        dst = g_Bc; di = n * 272 + k;
    } else {                               // v: K=272
        int j = i - 67584;
        int n = j / 272, k = j % 272;
        int kk = (k < 144) ? k : k + 128;
        w = Wv[kk * 128 + n];
        dst = g_Bv; di = n * 272 + k;
    }
    uint32_t t = f2tf32(w);
    dst[di] = __uint_as_float(t);
}

// ---------------- TF32 GEMM (R10-proven: BM=64 x BN=128, 3 CTAs/SM) ---------
#define BK 32
#define AST 36
#define A_BUF (64 * AST * 4)               // 9216 B
#define B_STG (128 * AST * 4)              // 18432 B
#define B_BASE (2 * A_BUF)                 // 18432
#define SMEM_TOTAL_TC (B_BASE + 3 * B_STG) // 73728

__global__ __launch_bounds__(256, 3) void tc_gemm(
    int M,
    const float* __restrict__ Af, int KF,
    const void* __restrict__ Ah, int ah_half,
    const float* __restrict__ Ae,
    const float* __restrict__ Bt,          // [128][Ktot] tf32 bits
    int Ktot,
    const float* __restrict__ bias, const float* __restrict__ Q,
    const int* __restrict__ qidx, int act,
    float* __restrict__ out, __half* __restrict__ out16)
{
    extern __shared__ char smem[];
    const uint32_t sb = smem_u32(smem);
    const int tid  = threadIdx.x;
    const int wid  = tid >> 5;
    const int lane = tid & 31;

    const int row0 = blockIdx.x * 64;

    const int r = tid >> 2;
    const int q = (tid & 3) * 8;
    int grow = row0 + r;
    if (grow >= M) grow = M - 1;

    const int brow = tid >> 1;
    const int bhf  = (tid & 1) * 16;
    const float* b_row = Bt + (size_t)brow * Ktot;

    const int nchunks = (Ktot + BK - 1) / BK;

    auto stage_b = [&](int c) {
        int s = c % 3;
        uint32_t dbase = sb + B_BASE + (uint32_t)s * B_STG +
                         (uint32_t)(brow * AST) * 4;
#pragma unroll
        for (int j2 = 0; j2 < 4; j2++) {
            int bq = bhf + j2 * 4;
            int gk = c * BK + bq;
            int rem = Ktot - gk;
            int sz = rem >= 4 ? 16 : 0;
            int gks = (rem >= 4) ? gk : (Ktot - 4);
            CP_ASYNC16(dbase + (uint32_t)bq * 4, b_row + gks, sz);
        }
    };

    auto load_a = [&](int c, float4* va) {
        int k0 = c * BK;
#pragma unroll
        for (int j = 0; j < 2; j++) {
            int gk = k0 + q + j * 4;
            float4 v = make_float4(0.f, 0.f, 0.f, 0.f);
            if (gk < KF) {
                v = *(const float4*)(Af + (size_t)grow * KF + gk);
            } else if (gk < KF + 128) {
                if (ah_half) {
                    uint2 raw = *(const uint2*)((const __half*)Ah +
                                                (size_t)grow * 128 + (gk - KF));
                    float2 a01 = __half22float2(*reinterpret_cast<__half2*>(&raw.x));
                    float2 a23 = __half22float2(*reinterpret_cast<__half2*>(&raw.y));
                    v = make_float4(a01.x, a01.y, a23.x, a23.y);
                } else {
                    v = *(const float4*)((const float*)Ah +
                                         (size_t)grow * 128 + (gk - KF));
                }
            } else if (gk < Ktot) {
                v = *(const float4*)(Ae + (size_t)grow * 128 + (gk - KF - 128));
            }
            va[j] = v;
        }
    };

    const int m_base = (wid & 1) * 32;
    const int n_base = (wid >> 1) * 32;
    float acc[2][4][4];
#pragma unroll
    for (int mt = 0; mt < 2; mt++)
#pragma unroll
        for (int nt = 0; nt < 4; nt++)
            acc[mt][nt][0] = acc[mt][nt][1] = acc[mt][nt][2] = acc[mt][nt][3] = 0.f;

    const int gr = lane >> 2;
    const int tc = lane & 3;

    stage_b(0); CP_COMMIT();
    float4 va[2];
    load_a(0, va);

    for (int c = 0; c < nchunks; c++) {
        const int abuf = c & 1;
        const uint32_t a_base = sb + (uint32_t)abuf * A_BUF;

#pragma unroll
        for (int j = 0; j < 2; j++) {
            uint4 t;
            t.x = f2tf32(va[j].x);
            t.y = f2tf32(va[j].y);
            t.z = f2tf32(va[j].z);
            t.w = f2tf32(va[j].w);
            *(uint4*)(smem + (a_base - sb) +
                      (uint32_t)(r * AST + q + j * 4) * 4) = t;
        }

        if (c + 1 < nchunks) {
            stage_b(c + 1); CP_COMMIT();
            load_a(c + 1, va);
            CP_WAIT(1);
        } else {
            CP_WAIT(0);
        }
        __syncthreads();

        const uint32_t b_base = sb + B_BASE + (uint32_t)(c % 3) * B_STG;

#pragma unroll
        for (int ks = 0; ks < 4; ks++) {
            const int k = ks * 8;
            uint32_t af[2][4];
#pragma unroll
            for (int mt = 0; mt < 2; mt++) {
                uint32_t r0 = a_base +
                    (uint32_t)((m_base + mt * 16 + gr) * AST + k + tc) * 4;
                uint32_t r1 = r0 + (uint32_t)(8 * AST) * 4;
                LDS32(af[mt][0], r0);
                LDS32(af[mt][1], r1);
                LDS32(af[mt][2], r0 + 16);
                LDS32(af[mt][3], r1 + 16);
            }
            uint32_t bf[4][2];
#pragma unroll
            for (int nt = 0; nt < 4; nt++) {
                uint32_t b0 = b_base +
                    (uint32_t)((n_base + nt * 8 + gr) * AST + k + tc) * 4;
                LDS32(bf[nt][0], b0);
                LDS32(bf[nt][1], b0 + 16);
            }
#pragma unroll
            for (int mt = 0; mt < 2; mt++)
#pragma unroll
                for (int nt = 0; nt < 4; nt++)
                    MMATF32(acc[mt][nt], af[mt], bf[nt][0], bf[nt][1]);
        }
    }

#pragma unroll
    for (int mt = 0; mt < 2; mt++) {
        int row_a = row0 + m_base + mt * 16 + gr;
        int row_b = row_a + 8;
        const float* qa = nullptr;
        const float* qb = nullptr;
        if (Q) {
            if (row_a < M) qa = Q + (size_t)qidx[row_a] * 128;
            if (row_b < M) qb = Q + (size_t)qidx[row_b] * 128;
        }
#pragma unroll
        for (int nt = 0; nt < 4; nt++) {
            int col = n_base + nt * 8 + tc * 2;
            float b0 = 0.f, b1 = 0.f;
            if (bias) { b0 = bias[col]; b1 = bias[col + 1]; }
            if (row_a < M) {
                float v0 = acc[mt][nt][0] + b0;
                float v1 = acc[mt][nt][1] + b1;
                if (qa) { v0 += qa[col]; v1 += qa[col + 1]; }
                if (act) { v0 = lrelu(v0); v1 = lrelu(v1); }
                if (out16) {
                    *(__half2*)(out16 + (size_t)row_a * 128 + col) =
                        __floats2half2_rn(v0, v1);
                } else {
                    *(float2*)(out + (size_t)row_a * 128 + col) =
                        make_float2(v0, v1);
                }
            }
            if (row_b < M) {
                float v0 = acc[mt][nt][2] + b0;
                float v1 = acc[mt][nt][3] + b1;
                if (qb) { v0 += qb[col]; v1 += qb[col + 1]; }
                if (act) { v0 = lrelu(v0); v1 = lrelu(v1); }
                if (out16) {
                    *(__half2*)(out16 + (size_t)row_b * 128 + col) =
                        __floats2half2_rn(v0, v1);
                } else {
                    *(float2*)(out + (size_t)row_b * 128 + col) =
                        make_float2(v0, v1);
                }
            }
        }
    }
}

// ---------------- small SIMT GEMM (tiny Q precomputes, M=64,K=128) ----------
__global__ __launch_bounds__(256, 2) void fused_gemm(
    int M,
    const float* __restrict__ Ah, const float* __restrict__ Wh,
    float* __restrict__ out)
{
    __shared__ float As[64][16];
    __shared__ float Ws[16][128];

    const int t  = threadIdx.x;
    const int tx = t & 31;
    const int ty = t >> 5;
    const int row0 = blockIdx.x * 64;

    float acc[8][4];
#pragma unroll
    for (int r = 0; r < 8; r++)
        acc[r][0] = acc[r][1] = acc[r][2] = acc[r][3] = 0.f;

    const int aRow = t >> 2;
    const int aK   = (t & 3) * 4;
    const int wK   = t >> 4;
    const int wC   = (t & 15) * 8;

    int arow_g = row0 + aRow;
    if (arow_g >= M) arow_g = M - 1;

    for (int kk = 0; kk < 128; kk += 16) {
        __syncthreads();
        float4 av = *(const float4*)(Ah + (size_t)arow_g * 128 + kk + aK);
        *(float4*)&As[aRow][aK] = av;
        const float* wp = Wh + (size_t)(kk + wK) * 128 + wC;
        *(float4*)&Ws[wK][wC]     = *(const float4*)(wp);
        *(float4*)&Ws[wK][wC + 4] = *(const float4*)(wp + 4);
        __syncthreads();

#pragma unroll
        for (int k = 0; k < 16; k++) {
            float4 w = *(const float4*)&Ws[k][tx * 4];
#pragma unroll
            for (int r = 0; r < 8; r++) {
                float a = As[ty * 8 + r][k];
                acc[r][0] = fmaf(a, w.x, acc[r][0]);
                acc[r][1] = fmaf(a, w.y, acc[r][1]);
                acc[r][2] = fmaf(a, w.z, acc[r][2]);
                acc[r][3] = fmaf(a, w.w, acc[r][3]);
            }
        }
    }

#pragma unroll
    for (int r = 0; r < 8; r++) {
        int row = row0 + ty * 8 + r;
        if (row < M) {
            float4 v = make_float4(acc[r][0], acc[r][1], acc[r][2], acc[r][3]);
            *(float4*)(out + (size_t)row * 128 + tx * 4) = v;
        }
    }
}

// ---------------- segment mean into NU=64 contexts --------------------------
__global__ __launch_bounds__(128) void seg_mean_ctx(
    const float* __restrict__ srcm, const int* __restrict__ ids, int n,
    float* __restrict__ acc, float* __restrict__ cntp)
{
    __shared__ float sacc[64 * 128];
    __shared__ float scnt[64];
    const int t = threadIdx.x;
    for (int i = t; i < 64 * 128; i += 128) sacc[i] = 0.f;
    if (t < 64) scnt[t] = 0.f;
    __syncthreads();

    for (long r0 = (long)blockIdx.x * 8; r0 < n; r0 += (long)gridDim.x * 8) {
        float v[8]; int id[8]; int k = 0;
#pragma unroll
        for (int u = 0; u < 8; u++) {
            long r = r0 + u;
            if (r < n) {
                id[k] = ids[r];
                v[k]  = srcm[(size_t)r * 128 + t];
                k++;
            }
        }
        for (int u = 0; u < k; u++) {
            sacc[id[u] * 128 + t] += v[u];
            if (t == 0) scnt[id[u]] += 1.f;
        }
    }
    __syncthreads();
    for (int i = t; i < 64 * 128; i += 128) atomicAdd(&acc[i], sacc[i]);
    if (t < 64) atomicAdd(&cntp[t], scnt[t]);
}

// ---------------- context update (64 rows, K=400) ---------------------------
__global__ __launch_bounds__(128) void ctx_update(
    const float* __restrict__ ctx_feats,
    const float* __restrict__ ctx_emb,
    const float* __restrict__ acc,
    const float* __restrict__ cntp,
    const float* __restrict__ Wu,
    const float* __restrict__ bu,
    float* __restrict__ out)
{
    const int u = blockIdx.x;
    const int t = threadIdx.x;
    __shared__ float a[400];

    if (t < 16) a[t] = ctx_feats[u * 16 + t];
    float cc = fmaxf(cntp[u], 1.f);
    float cv = fmaxf(cntp[64 + u], 1.f);
    a[16 + t]  = acc[u * 128 + t] / cc;
    a[144 + t] = acc[64 * 128 + u * 128 + t] / cv;
    a[272 + t] = ctx_emb[u * 128 + t];
    __syncthreads();

    float s = bu[t];
    for (int k = 0; k < 400; k++) s = fmaf(a[k], Wu[k * 128 + t], s);
    out[(size_t)u * 128 + t] = lrelu(s);
}

// ---------------- launch ----------------------------------------------------
extern "C" void kernel_launch(void* const* d_in, const int* in_sizes, int n_in,
                              void* d_out, int out_size)
{
    const float* var_emb      = (const float*)d_in[0];
    const float* clause_emb   = (const float*)d_in[1];
    const float* ctx_emb      = (const float*)d_in[2];
    const float* var_feats    = (const float*)d_in[3];
    const float* clause_feats = (const float*)d_in[4];
    const float* ctx_feats    = (const float*)d_in[5];
    const float* edge_sat_vc  = (const float*)d_in[6];
    const float* edge_sat_cv  = (const float*)d_in[7];
    const float* W_vc         = (const float*)d_in[8];
    const float* b_vc         = (const float*)d_in[9];
    const float* W_cv         = (const float*)d_in[10];
    const float* b_cv         = (const float*)d_in[11];
    const float* W_c          = (const float*)d_in[12];
    const float* b_c          = (const float*)d_in[13];
    const float* W_v          = (const float*)d_in[14];
    const float* b_v          = (const float*)d_in[15];
    const float* W_u          = (const float*)d_in[16];
    const float* b_u          = (const float*)d_in[17];
    const int* assigns_src    = (const int*)d_in[18];
    const int* assigns_dst    = (const int*)d_in[19];
    const int* contains_src   = (const int*)d_in[20];
    const int* contains_dst   = (const int*)d_in[21];
    const int* var_ctx        = (const int*)d_in[22];
    const int* clause_ctx     = (const int*)d_in[23];

    const int NV = in_sizes[0] / C_D;
    const int NC = in_sizes[1] / C_D;
    const int E  = in_sizes[18];
    const int NN = NC + NV;

    float *Qc, *Qv, *cacc, *ccnt;
    __half *Pv, *Pc, *hc, *hv;
    cudaGetSymbolAddress((void**)&hc,   g_hc);
    cudaGetSymbolAddress((void**)&hv,   g_hv);
    cudaGetSymbolAddress((void**)&Pv,   g_Pv);
    cudaGetSymbolAddress((void**)&Pc,   g_Pc);
    cudaGetSymbolAddress((void**)&Qc,   g_Qc);
    cudaGetSymbolAddress((void**)&Qv,   g_Qv);
    cudaGetSymbolAddress((void**)&cacc, g_ctx_acc);
    cudaGetSymbolAddress((void**)&ccnt, g_ctx_cnt);

    int *deg, *fill, *bsum;
    uint4 *sedge1, *sedge2;
    cudaGetSymbolAddress((void**)&deg,    g_deg);
    cudaGetSymbolAddress((void**)&fill,   g_fill);
    cudaGetSymbolAddress((void**)&bsum,   g_bsum);
    cudaGetSymbolAddress((void**)&sedge1, g_sedge1);
    cudaGetSymbolAddress((void**)&sedge2, g_sedge2);

    float *Bvc, *Bcv, *Bc, *Bv;
    cudaGetSymbolAddress((void**)&Bvc, g_Bvc);
    cudaGetSymbolAddress((void**)&Bcv, g_Bcv);
    cudaGetSymbolAddress((void**)&Bc,  g_Bc);
    cudaGetSymbolAddress((void**)&Bv,  g_Bv);

    float* out = (float*)d_out;

    cudaFuncSetAttribute(tc_gemm, cudaFuncAttributeMaxDynamicSharedMemorySize,
                         SMEM_TOTAL_TC);

    const int nb = (NN + 4095) / 4096;   // scan blocks

    // Second stream (non-blocking so legacy-stream implicit sync doesn't
    // serialize it) + fork/join events. Created fresh each call; the harness
    // calls kernel_launch twice (eager + capture), so this is bounded.
    cudaStream_t s1;
    cudaStreamCreateWithFlags(&s1, cudaStreamNonBlocking);
    cudaEvent_t evZero, evPrep, evNC, evSMC;
    cudaEventCreateWithFlags(&evZero, cudaEventDisableTiming);
    cudaEventCreateWithFlags(&evPrep, cudaEventDisableTiming);
    cudaEventCreateWithFlags(&evNC,   cudaEventDisableTiming);
    cudaEventCreateWithFlags(&evSMC,  cudaEventDisableTiming);

    // ---- s0 (default/capture stream) ----
    // 1. zero small accumulators (deg, fill, ctx)
    zero_small<<<512, 256>>>(deg, fill, cacc, ccnt);
    cudaEventRecord(evZero, 0);
    // 2. weight transpose + tf32 rounding
    wprep<<<(102400 + 255) / 256, 256>>>(W_vc, W_cv, W_c, W_v);
    // 3. P_v (TF32, fp16 out)
    tc_gemm<<<(NV + 63) / 64, 256, SMEM_TOTAL_TC>>>(
        NV, nullptr, 0, var_emb, 0, nullptr,
        Bvc, 128, nullptr, nullptr, nullptr, 0, nullptr, Pv);
    // 4. P_c (TF32, fp16 out) <-- ncu control point
    tc_gemm<<<(NC + 63) / 64, 256, SMEM_TOTAL_TC>>>(
        NC, nullptr, 0, clause_emb, 0, nullptr,
        Bcv, 128, nullptr, nullptr, nullptr, 0, nullptr, Pc);

    // ---- s1: edge prep + Q precomputes, overlapped under P GEMMs ----
    cudaStreamWaitEvent(s1, evZero, 0);
    hist_kernel<<<(2 * E + 255) / 256, 256, 0, s1>>>(
        E, assigns_dst, contains_dst, deg);
    scanA<<<nb, 256, 0, s1>>>(deg, NN, deg, bsum);
    scanB<<<1, 32, 0, s1>>>(bsum, nb);
    scanC<<<(NN + 255) / 256, 256, 0, s1>>>(deg, bsum, NN);
    scatter_kernel<<<(2 * E + 255) / 256, 256, 0, s1>>>(
        E, assigns_src, assigns_dst, (const float4*)edge_sat_vc,
        contains_src, contains_dst, (const float4*)edge_sat_cv,
        deg, fill, sedge1, sedge2);
    fused_gemm<<<1, 256, 0, s1>>>(C_NU, ctx_emb, W_c + 144 * C_D, Qc);
    fused_gemm<<<1, 256, 0, s1>>>(C_NU, ctx_emb, W_v + 144 * C_D, Qv);
    cudaEventRecord(evPrep, s1);

    // ---- s0: aggregates + node GEMMs ----
    cudaStreamWaitEvent(0, evPrep, 0);
    agg_kernel<<<(NC + 7) / 8, 256>>>(
        NC, 0, 0, deg, fill, sedge1, Pv, W_vc, b_vc, hc);
    agg_kernel<<<(NV + 7) / 8, 256>>>(
        NV, NC, E, deg, fill, sedge2, Pc, W_cv, b_cv, hv);

    // new_clause -> out rows [0, NC)
    tc_gemm<<<(NC + 63) / 64, 256, SMEM_TOTAL_TC>>>(
        NC, clause_feats, 16, hc, 1, clause_emb,
        Bc, 272, b_c, Qc, clause_ctx, 1, out, nullptr);
    cudaEventRecord(evNC, 0);

    // s1: seg_mean over clause rows, overlapped with node_var GEMM on s0
    cudaStreamWaitEvent(s1, evNC, 0);
    seg_mean_ctx<<<2048, 128, 0, s1>>>(out, clause_ctx, NC, cacc, ccnt);
    cudaEventRecord(evSMC, s1);

    // s0: new_var -> out rows [NC, NC+NV)
    tc_gemm<<<(NV + 63) / 64, 256, SMEM_TOTAL_TC>>>(
        NV, var_feats, 16, hv, 1, var_emb,
        Bv, 272, b_v, Qv, var_ctx, 1, out + (size_t)NC * C_D, nullptr);
    // s0: seg_mean over var rows
    seg_mean_ctx<<<2048, 128>>>(out + (size_t)NC * C_D, var_ctx, NV,
                                cacc + C_NU * C_D, ccnt + C_NU);

    // join s1, then final context update on s0
    cudaStreamWaitEvent(0, evSMC, 0);
    ctx_update<<<C_NU, 128>>>(ctx_feats, ctx_emb, cacc, ccnt, W_u, b_u,
                              out + (size_t)(NC + NV) * C_D);
}

// round 14
// speedup vs baseline: 1.2699x; 1.0317x over previous
#include <cuda_runtime.h>
#include <cuda_fp16.h>
#include <cstdint>

// Problem constants (fixed by the dataset)
#define C_NV 100000
#define C_NC 400000
#define C_NU 64
#define C_E  1200000
#define C_D  128
#define C_NN (C_NC + C_NV)          // concatenated node count for degree/scan

// ---------------- scratch (device globals; no allocation allowed) ----------
__device__ __align__(16) __half g_hc[(size_t)C_NC * C_D];  // clause message means
__device__ __align__(16) __half g_hv[(size_t)C_NV * C_D];  // var message means
__device__ __align__(16) __half g_Pv[(size_t)C_NV * C_D];  // var_emb @ W_vc[4:132]
__device__ __align__(16) __half g_Pc[(size_t)C_NC * C_D];  // clause_emb @ W_cv[4:132]
__device__ float g_Qc[C_NU * C_D];             // ctx_emb @ W_c[144:272]
__device__ float g_Qv[C_NU * C_D];             // ctx_emb @ W_v[144:272]
__device__ float g_ctx_acc[2 * C_NU * C_D];    // [clause sums | var sums]
__device__ float g_ctx_cnt[2 * C_NU];

// CSR edge binning: packed records {src, pad, es01(h2), es23(h2)} = 16 B
__device__ int   g_deg[C_NN];                  // degrees -> exclusive scan (base)
__device__ int   g_fill[C_NN];                 // scatter cursors (== deg after)
__device__ int   g_bsum[256];                  // scan block sums
__device__ __align__(16) uint4 g_sedge1[C_E];  // dir1 (var->clause)
__device__ __align__(16) uint4 g_sedge2[C_E];  // dir2 (clause->var)

// Transposed tf32-rounded weights: layout [n (0..127)][k (0..K-1)], fp32 bits
__device__ __align__(16) float g_Bvc[128 * 128];
__device__ __align__(16) float g_Bcv[128 * 128];
__device__ __align__(16) float g_Bc[128 * 272];
__device__ __align__(16) float g_Bv[128 * 272];

static __device__ __forceinline__ float lrelu(float x) {
    return x >= 0.f ? x : 0.1f * x;
}

static __device__ __forceinline__ uint32_t smem_u32(const void* p) {
    uint32_t a;
    asm("{ .reg .u64 t; cvta.to.shared.u64 t, %1; cvt.u32.u64 %0, t; }"
        : "=r"(a) : "l"(p));
    return a;
}

static __device__ __forceinline__ uint32_t f2tf32(float f) {
    uint32_t u;
    asm("cvt.rna.tf32.f32 %0, %1;" : "=r"(u) : "f"(f));
    return u;
}

#define LDS32(d, addr)                                                         \
    asm volatile("ld.shared.b32 %0, [%1];" : "=r"(d) : "r"(addr))

// mma.sync m16n8k8 tf32 -> fp32
#define MMATF32(c, a, b0, b1)                                                  \
    asm volatile(                                                              \
        "mma.sync.aligned.m16n8k8.row.col.f32.tf32.tf32.f32 "                  \
        "{%0,%1,%2,%3}, {%4,%5,%6,%7}, {%8,%9}, {%0,%1,%2,%3};"                \
        : "+f"((c)[0]), "+f"((c)[1]), "+f"((c)[2]), "+f"((c)[3])               \
        : "r"((a)[0]), "r"((a)[1]), "r"((a)[2]), "r"((a)[3]),                  \
          "r"(b0), "r"(b1))

#define CP_ASYNC16(dst, src, sz)                                               \
    asm volatile("cp.async.cg.shared.global [%0], [%1], 16, %2;"               \
                 :: "r"(dst), "l"(src), "r"(sz))
#define CP_COMMIT() asm volatile("cp.async.commit_group;" ::: "memory")
#define CP_WAIT(n)  asm volatile("cp.async.wait_group %0;" :: "n"(n) : "memory")

// ---------------- zero small accumulators ------------------------------------
__global__ void zero_small(int* deg, int* fill, float* cacc, float* ccnt)
{
    int i = blockIdx.x * blockDim.x + threadIdx.x;
    int stride = gridDim.x * blockDim.x;
    for (int j = i; j < C_NN; j += stride) { deg[j] = 0; fill[j] = 0; }
    for (int j = i; j < 2 * C_NU * C_D; j += stride) cacc[j] = 0.f;
    if (i < 2 * C_NU) ccnt[i] = 0.f;
}

// ---------------- histogram of destinations ---------------------------------
__global__ void hist_kernel(int E, const int* __restrict__ dst1,
                            const int* __restrict__ dst2, int* __restrict__ deg)
{
    int i = blockIdx.x * blockDim.x + threadIdx.x;
    if (i < E)          atomicAdd(&deg[dst1[i]], 1);
    else if (i < 2 * E) atomicAdd(&deg[C_NC + dst2[i - E]], 1);
}

// ---------------- exclusive scan (3 kernels, 4096/block) ---------------------
__global__ void scanA(const int* __restrict__ deg, int n,
                      int* __restrict__ base, int* __restrict__ bsum)
{
    __shared__ int tsum[256];
    const int t = threadIdx.x;
    const int b0 = blockIdx.x * 4096;
    int v[16];
    int s = 0;
#pragma unroll
    for (int j = 0; j < 16; j++) {
        int idx = b0 + t * 16 + j;
        v[j] = (idx < n) ? deg[idx] : 0;
        s += v[j];
    }
    tsum[t] = s;
    __syncthreads();
    for (int off = 1; off < 256; off <<= 1) {
        int u = (t >= off) ? tsum[t - off] : 0;
        __syncthreads();
        tsum[t] += u;
        __syncthreads();
    }
    int run = tsum[t] - s;
#pragma unroll
    for (int j = 0; j < 16; j++) {
        int idx = b0 + t * 16 + j;
        if (idx < n) base[idx] = run;
        run += v[j];
    }
    if (t == 255) bsum[blockIdx.x] = tsum[255];
}

__global__ void scanB(int* bsum, int nb)
{
    if (threadIdx.x == 0 && blockIdx.x == 0) {
        int r = 0;
        for (int i = 0; i < nb; i++) { int d = bsum[i]; bsum[i] = r; r += d; }
    }
}

__global__ void scanC(int* __restrict__ base, const int* __restrict__ bsum, int n)
{
    int i = blockIdx.x * blockDim.x + threadIdx.x;
    if (i < n) base[i] += bsum[i >> 12];
}

// ---------------- scatter edges into destination order ----------------------
__global__ void scatter_kernel(
    int E,
    const int* __restrict__ src1, const int* __restrict__ dst1,
    const float4* __restrict__ es1,
    const int* __restrict__ src2, const int* __restrict__ dst2,
    const float4* __restrict__ es2,
    const int* __restrict__ base, int* __restrict__ fill,
    uint4* __restrict__ sedge1, uint4* __restrict__ sedge2)
{
    int i = blockIdx.x * blockDim.x + threadIdx.x;
    if (i < E) {
        int d = dst1[i];
        int p = base[d] + atomicAdd(&fill[d], 1);
        float4 ev = es1[i];
        __half2 h01 = __floats2half2_rn(ev.x, ev.y);
        __half2 h23 = __floats2half2_rn(ev.z, ev.w);
        uint4 rec;
        rec.x = (uint32_t)src1[i];
        rec.y = 0u;
        rec.z = *reinterpret_cast<uint32_t*>(&h01);
        rec.w = *reinterpret_cast<uint32_t*>(&h23);
        sedge1[p] = rec;
    } else if (i < 2 * E) {
        int e = i - E;
        int d = C_NC + dst2[e];
        int p = base[d] + atomicAdd(&fill[d], 1) - E;
        float4 ev = es2[e];
        __half2 h01 = __floats2half2_rn(ev.x, ev.y);
        __half2 h23 = __floats2half2_rn(ev.z, ev.w);
        uint4 rec;
        rec.x = (uint32_t)src2[e];
        rec.y = 0u;
        rec.z = *reinterpret_cast<uint32_t*>(&h01);
        rec.w = *reinterpret_cast<uint32_t*>(&h23);
        sedge2[p] = rec;
    }
}

// ---------------- CSR aggregate: warp per destination node ------------------
__global__ __launch_bounds__(256) void agg_kernel(
    int N0, int baseoff, int posoff,
    const int* __restrict__ base, const int* __restrict__ fill,
    const uint4* __restrict__ sedge,
    const __half* __restrict__ P,
    const float* __restrict__ W1, const float* __restrict__ b,
    __half* __restrict__ outh)
{
    const int warp = blockIdx.x * 8 + (threadIdx.x >> 5);
    if (warp >= N0) return;
    const int lane = threadIdx.x & 31;
    const int c = lane * 4;

    float w[4][4], bb[4];
#pragma unroll
    for (int r = 0; r < 4; r++)
#pragma unroll
        for (int i = 0; i < 4; i++)
            w[r][i] = W1[r * 128 + c + i];
#pragma unroll
    for (int i = 0; i < 4; i++) bb[i] = b[c + i];

    const int start = base[baseoff + warp] - posoff;
    const int deg   = fill[baseoff + warp];

    float s0 = 0.f, s1 = 0.f, s2 = 0.f, s3 = 0.f;

    auto edge_term = [&](uint4 rec, uint2 praw) {
        float2 e01 = __half22float2(*reinterpret_cast<__half2*>(&rec.z));
        float2 e23 = __half22float2(*reinterpret_cast<__half2*>(&rec.w));
        float2 p01 = __half22float2(*reinterpret_cast<__half2*>(&praw.x));
        float2 p23 = __half22float2(*reinterpret_cast<__half2*>(&praw.y));
        float m0 = bb[0], m1 = bb[1], m2 = bb[2], m3 = bb[3];
        m0 = fmaf(e01.x, w[0][0], m0); m0 = fmaf(e01.y, w[1][0], m0);
        m0 = fmaf(e23.x, w[2][0], m0); m0 = fmaf(e23.y, w[3][0], m0);
        m1 = fmaf(e01.x, w[0][1], m1); m1 = fmaf(e01.y, w[1][1], m1);
        m1 = fmaf(e23.x, w[2][1], m1); m1 = fmaf(e23.y, w[3][1], m1);
        m2 = fmaf(e01.x, w[0][2], m2); m2 = fmaf(e01.y, w[1][2], m2);
        m2 = fmaf(e23.x, w[2][2], m2); m2 = fmaf(e23.y, w[3][2], m2);
        m3 = fmaf(e01.x, w[0][3], m3); m3 = fmaf(e01.y, w[1][3], m3);
        m3 = fmaf(e23.x, w[2][3], m3); m3 = fmaf(e23.y, w[3][3], m3);
        s0 += lrelu(m0 + p01.x);
        s1 += lrelu(m1 + p01.y);
        s2 += lrelu(m2 + p23.x);
        s3 += lrelu(m3 + p23.y);
    };

    int j = 0;
    for (; j + 4 <= deg; j += 4) {
        uint4 r0 = sedge[start + j + 0];
        uint4 r1 = sedge[start + j + 1];
        uint4 r2 = sedge[start + j + 2];
        uint4 r3 = sedge[start + j + 3];
        uint2 q0 = *(const uint2*)(P + (size_t)r0.x * 128 + c);
        uint2 q1 = *(const uint2*)(P + (size_t)r1.x * 128 + c);
        uint2 q2 = *(const uint2*)(P + (size_t)r2.x * 128 + c);
        uint2 q3 = *(const uint2*)(P + (size_t)r3.x * 128 + c);
        edge_term(r0, q0);
        edge_term(r1, q1);
        edge_term(r2, q2);
        edge_term(r3, q3);
    }
    for (; j < deg; j++) {
        uint4 r0 = sedge[start + j];
        uint2 q0 = *(const uint2*)(P + (size_t)r0.x * 128 + c);
        edge_term(r0, q0);
    }

    float inv = (deg > 0) ? (1.f / (float)deg) : 0.f;
    __half2 o01 = __floats2half2_rn(s0 * inv, s1 * inv);
    __half2 o23 = __floats2half2_rn(s2 * inv, s3 * inv);
    uint2 pk;
    pk.x = *reinterpret_cast<uint32_t*>(&o01);
    pk.y = *reinterpret_cast<uint32_t*>(&o23);
    *(uint2*)(outh + (size_t)warp * 128 + c) = pk;
}

// ---------------- weight transpose + tf32 rounding --------------------------
__global__ void wprep(const float* __restrict__ Wvc, const float* __restrict__ Wcv,
                      const float* __restrict__ Wc,  const float* __restrict__ Wv)
{
    int i = blockIdx.x * blockDim.x + threadIdx.x;
    if (i >= 102400) return;
    float w;
    float* dst;
    int di;
    if (i < 16384) {                       // vc: K=128, W rows 4..131
        int n = i >> 7, k = i & 127;
        w = Wvc[(4 + k) * 128 + n];
        dst = g_Bvc; di = n * 128 + k;
    } else if (i < 32768) {                // cv: K=128, W rows 4..131
        int j = i - 16384;
        int n = j >> 7, k = j & 127;
        w = Wcv[(4 + k) * 128 + n];
        dst = g_Bcv; di = n * 128 + k;
    } else if (i < 67584) {                // c: K=272, W rows {0..143, 272..399}
        int j = i - 32768;
        int n = j / 272, k = j % 272;
        int kk = (k < 144) ? k : k + 128;
        w = Wc[kk * 128 + n];
        dst = g_Bc; di = n * 272 + k;
    } else {                               // v: K=272
        int j = i - 67584;
        int n = j / 272, k = j % 272;
        int kk = (k < 144) ? k : k + 128;
        w = Wv[kk * 128 + n];
        dst = g_Bv; di = n * 272 + k;
    }
    uint32_t t = f2tf32(w);
    dst[di] = __uint_as_float(t);
}

// ---------------- TF32 GEMM (R10-proven: BM=64 x BN=128, 3 CTAs/SM) ---------
#define BK 32
#define AST 36
#define A_BUF (64 * AST * 4)               // 9216 B
#define B_STG (128 * AST * 4)              // 18432 B
#define B_BASE (2 * A_BUF)                 // 18432
#define SMEM_TOTAL_TC (B_BASE + 3 * B_STG) // 73728

__global__ __launch_bounds__(256, 3) void tc_gemm(
    int M,
    const float* __restrict__ Af, int KF,
    const void* __restrict__ Ah, int ah_half,
    const float* __restrict__ Ae,
    const float* __restrict__ Bt,          // [128][Ktot] tf32 bits
    int Ktot,
    const float* __restrict__ bias, const float* __restrict__ Q,
    const int* __restrict__ qidx, int act,
    float* __restrict__ out, __half* __restrict__ out16)
{
    extern __shared__ char smem[];
    const uint32_t sb = smem_u32(smem);
    const int tid  = threadIdx.x;
    const int wid  = tid >> 5;
    const int lane = tid & 31;

    const int row0 = blockIdx.x * 64;

    const int r = tid >> 2;
    const int q = (tid & 3) * 8;
    int grow = row0 + r;
    if (grow >= M) grow = M - 1;

    const int brow = tid >> 1;
    const int bhf  = (tid & 1) * 16;
    const float* b_row = Bt + (size_t)brow * Ktot;

    const int nchunks = (Ktot + BK - 1) / BK;

    auto stage_b = [&](int c) {
        int s = c % 3;
        uint32_t dbase = sb + B_BASE + (uint32_t)s * B_STG +
                         (uint32_t)(brow * AST) * 4;
#pragma unroll
        for (int j2 = 0; j2 < 4; j2++) {
            int bq = bhf + j2 * 4;
            int gk = c * BK + bq;
            int rem = Ktot - gk;
            int sz = rem >= 4 ? 16 : 0;
            int gks = (rem >= 4) ? gk : (Ktot - 4);
            CP_ASYNC16(dbase + (uint32_t)bq * 4, b_row + gks, sz);
        }
    };

    auto load_a = [&](int c, float4* va) {
        int k0 = c * BK;
#pragma unroll
        for (int j = 0; j < 2; j++) {
            int gk = k0 + q + j * 4;
            float4 v = make_float4(0.f, 0.f, 0.f, 0.f);
            if (gk < KF) {
                v = *(const float4*)(Af + (size_t)grow * KF + gk);
            } else if (gk < KF + 128) {
                if (ah_half) {
                    uint2 raw = *(const uint2*)((const __half*)Ah +
                                                (size_t)grow * 128 + (gk - KF));
                    float2 a01 = __half22float2(*reinterpret_cast<__half2*>(&raw.x));
                    float2 a23 = __half22float2(*reinterpret_cast<__half2*>(&raw.y));
                    v = make_float4(a01.x, a01.y, a23.x, a23.y);
                } else {
                    v = *(const float4*)((const float*)Ah +
                                         (size_t)grow * 128 + (gk - KF));
                }
            } else if (gk < Ktot) {
                v = *(const float4*)(Ae + (size_t)grow * 128 + (gk - KF - 128));
            }
            va[j] = v;
        }
    };

    const int m_base = (wid & 1) * 32;
    const int n_base = (wid >> 1) * 32;
    float acc[2][4][4];
#pragma unroll
    for (int mt = 0; mt < 2; mt++)
#pragma unroll
        for (int nt = 0; nt < 4; nt++)
            acc[mt][nt][0] = acc[mt][nt][1] = acc[mt][nt][2] = acc[mt][nt][3] = 0.f;

    const int gr = lane >> 2;
    const int tc = lane & 3;

    stage_b(0); CP_COMMIT();
    float4 va[2];
    load_a(0, va);

    for (int c = 0; c < nchunks; c++) {
        const int abuf = c & 1;
        const uint32_t a_base = sb + (uint32_t)abuf * A_BUF;

#pragma unroll
        for (int j = 0; j < 2; j++) {
            uint4 t;
            t.x = f2tf32(va[j].x);
            t.y = f2tf32(va[j].y);
            t.z = f2tf32(va[j].z);
            t.w = f2tf32(va[j].w);
            *(uint4*)(smem + (a_base - sb) +
                      (uint32_t)(r * AST + q + j * 4) * 4) = t;
        }

        if (c + 1 < nchunks) {
            stage_b(c + 1); CP_COMMIT();
            load_a(c + 1, va);
            CP_WAIT(1);
        } else {
            CP_WAIT(0);
        }
        __syncthreads();

        const uint32_t b_base = sb + B_BASE + (uint32_t)(c % 3) * B_STG;

#pragma unroll
        for (int ks = 0; ks < 4; ks++) {
            const int k = ks * 8;
            uint32_t af[2][4];
#pragma unroll
            for (int mt = 0; mt < 2; mt++) {
                uint32_t r0 = a_base +
                    (uint32_t)((m_base + mt * 16 + gr) * AST + k + tc) * 4;
                uint32_t r1 = r0 + (uint32_t)(8 * AST) * 4;
                LDS32(af[mt][0], r0);
                LDS32(af[mt][1], r1);
                LDS32(af[mt][2], r0 + 16);
                LDS32(af[mt][3], r1 + 16);
            }
            uint32_t bf[4][2];
#pragma unroll
            for (int nt = 0; nt < 4; nt++) {
                uint32_t b0 = b_base +
                    (uint32_t)((n_base + nt * 8 + gr) * AST + k + tc) * 4;
                LDS32(bf[nt][0], b0);
                LDS32(bf[nt][1], b0 + 16);
            }
#pragma unroll
            for (int mt = 0; mt < 2; mt++)
#pragma unroll
                for (int nt = 0; nt < 4; nt++)
                    MMATF32(acc[mt][nt], af[mt], bf[nt][0], bf[nt][1]);
        }
    }

#pragma unroll
    for (int mt = 0; mt < 2; mt++) {
        int row_a = row0 + m_base + mt * 16 + gr;
        int row_b = row_a + 8;
        const float* qa = nullptr;
        const float* qb = nullptr;
        if (Q) {
            if (row_a < M) qa = Q + (size_t)qidx[row_a] * 128;
            if (row_b < M) qb = Q + (size_t)qidx[row_b] * 128;
        }
#pragma unroll
        for (int nt = 0; nt < 4; nt++) {
            int col = n_base + nt * 8 + tc * 2;
            float b0 = 0.f, b1 = 0.f;
            if (bias) { b0 = bias[col]; b1 = bias[col + 1]; }
            if (row_a < M) {
                float v0 = acc[mt][nt][0] + b0;
                float v1 = acc[mt][nt][1] + b1;
                if (qa) { v0 += qa[col]; v1 += qa[col + 1]; }
                if (act) { v0 = lrelu(v0); v1 = lrelu(v1); }
                if (out16) {
                    *(__half2*)(out16 + (size_t)row_a * 128 + col) =
                        __floats2half2_rn(v0, v1);
                } else {
                    *(float2*)(out + (size_t)row_a * 128 + col) =
                        make_float2(v0, v1);
                }
            }
            if (row_b < M) {
                float v0 = acc[mt][nt][2] + b0;
                float v1 = acc[mt][nt][3] + b1;
                if (qb) { v0 += qb[col]; v1 += qb[col + 1]; }
                if (act) { v0 = lrelu(v0); v1 = lrelu(v1); }
                if (out16) {
                    *(__half2*)(out16 + (size_t)row_b * 128 + col) =
                        __floats2half2_rn(v0, v1);
                } else {
                    *(float2*)(out + (size_t)row_b * 128 + col) =
                        make_float2(v0, v1);
                }
            }
        }
    }
}

// ---------------- small SIMT GEMM (tiny Q precomputes, M=64,K=128) ----------
__global__ __launch_bounds__(256, 2) void fused_gemm(
    int M,
    const float* __restrict__ Ah, const float* __restrict__ Wh,
    float* __restrict__ out)
{
    __shared__ float As[64][16];
    __shared__ float Ws[16][128];

    const int t  = threadIdx.x;
    const int tx = t & 31;
    const int ty = t >> 5;
    const int row0 = blockIdx.x * 64;

    float acc[8][4];
#pragma unroll
    for (int r = 0; r < 8; r++)
        acc[r][0] = acc[r][1] = acc[r][2] = acc[r][3] = 0.f;

    const int aRow = t >> 2;
    const int aK   = (t & 3) * 4;
    const int wK   = t >> 4;
    const int wC   = (t & 15) * 8;

    int arow_g = row0 + aRow;
    if (arow_g >= M) arow_g = M - 1;

    for (int kk = 0; kk < 128; kk += 16) {
        __syncthreads();
        float4 av = *(const float4*)(Ah + (size_t)arow_g * 128 + kk + aK);
        *(float4*)&As[aRow][aK] = av;
        const float* wp = Wh + (size_t)(kk + wK) * 128 + wC;
        *(float4*)&Ws[wK][wC]     = *(const float4*)(wp);
        *(float4*)&Ws[wK][wC + 4] = *(const float4*)(wp + 4);
        __syncthreads();

#pragma unroll
        for (int k = 0; k < 16; k++) {
            float4 w = *(const float4*)&Ws[k][tx * 4];
#pragma unroll
            for (int r = 0; r < 8; r++) {
                float a = As[ty * 8 + r][k];
                acc[r][0] = fmaf(a, w.x, acc[r][0]);
                acc[r][1] = fmaf(a, w.y, acc[r][1]);
                acc[r][2] = fmaf(a, w.z, acc[r][2]);
                acc[r][3] = fmaf(a, w.w, acc[r][3]);
            }
        }
    }

#pragma unroll
    for (int r = 0; r < 8; r++) {
        int row = row0 + ty * 8 + r;
        if (row < M) {
            float4 v = make_float4(acc[r][0], acc[r][1], acc[r][2], acc[r][3]);
            *(float4*)(out + (size_t)row * 128 + tx * 4) = v;
        }
    }
}

// ---------------- segment mean into NU=64 contexts --------------------------
__global__ __launch_bounds__(128) void seg_mean_ctx(
    const float* __restrict__ srcm, const int* __restrict__ ids, int n,
    float* __restrict__ acc, float* __restrict__ cntp)
{
    __shared__ float sacc[64 * 128];
    __shared__ float scnt[64];
    const int t = threadIdx.x;
    for (int i = t; i < 64 * 128; i += 128) sacc[i] = 0.f;
    if (t < 64) scnt[t] = 0.f;
    __syncthreads();

    for (long r0 = (long)blockIdx.x * 8; r0 < n; r0 += (long)gridDim.x * 8) {
        float v[8]; int id[8]; int k = 0;
#pragma unroll
        for (int u = 0; u < 8; u++) {
            long r = r0 + u;
            if (r < n) {
                id[k] = ids[r];
                v[k]  = srcm[(size_t)r * 128 + t];
                k++;
            }
        }
        for (int u = 0; u < k; u++) {
            sacc[id[u] * 128 + t] += v[u];
            if (t == 0) scnt[id[u]] += 1.f;
        }
    }
    __syncthreads();
    for (int i = t; i < 64 * 128; i += 128) atomicAdd(&acc[i], sacc[i]);
    if (t < 64) atomicAdd(&cntp[t], scnt[t]);
}

// ---------------- context update (64 rows, K=400) ---------------------------
__global__ __launch_bounds__(128) void ctx_update(
    const float* __restrict__ ctx_feats,
    const float* __restrict__ ctx_emb,
    const float* __restrict__ acc,
    const float* __restrict__ cntp,
    const float* __restrict__ Wu,
    const float* __restrict__ bu,
    float* __restrict__ out)
{
    const int u = blockIdx.x;
    const int t = threadIdx.x;
    __shared__ float a[400];

    if (t < 16) a[t] = ctx_feats[u * 16 + t];
    float cc = fmaxf(cntp[u], 1.f);
    float cv = fmaxf(cntp[64 + u], 1.f);
    a[16 + t]  = acc[u * 128 + t] / cc;
    a[144 + t] = acc[64 * 128 + u * 128 + t] / cv;
    a[272 + t] = ctx_emb[u * 128 + t];
    __syncthreads();

    float s = bu[t];
    for (int k = 0; k < 400; k++) s = fmaf(a[k], Wu[k * 128 + t], s);
    out[(size_t)u * 128 + t] = lrelu(s);
}

// ---------------- launch ----------------------------------------------------
extern "C" void kernel_launch(void* const* d_in, const int* in_sizes, int n_in,
                              void* d_out, int out_size)
{
    const float* var_emb      = (const float*)d_in[0];
    const float* clause_emb   = (const float*)d_in[1];
    const float* ctx_emb      = (const float*)d_in[2];
    const float* var_feats    = (const float*)d_in[3];
    const float* clause_feats = (const float*)d_in[4];
    const float* ctx_feats    = (const float*)d_in[5];
    const float* edge_sat_vc  = (const float*)d_in[6];
    const float* edge_sat_cv  = (const float*)d_in[7];
    const float* W_vc         = (const float*)d_in[8];
    const float* b_vc         = (const float*)d_in[9];
    const float* W_cv         = (const float*)d_in[10];
    const float* b_cv         = (const float*)d_in[11];
    const float* W_c          = (const float*)d_in[12];
    const float* b_c          = (const float*)d_in[13];
    const float* W_v          = (const float*)d_in[14];
    const float* b_v          = (const float*)d_in[15];
    const float* W_u          = (const float*)d_in[16];
    const float* b_u          = (const float*)d_in[17];
    const int* assigns_src    = (const int*)d_in[18];
    const int* assigns_dst    = (const int*)d_in[19];
    const int* contains_src   = (const int*)d_in[20];
    const int* contains_dst   = (const int*)d_in[21];
    const int* var_ctx        = (const int*)d_in[22];
    const int* clause_ctx     = (const int*)d_in[23];

    const int NV = in_sizes[0] / C_D;
    const int NC = in_sizes[1] / C_D;
    const int E  = in_sizes[18];
    const int NN = NC + NV;

    float *Qc, *Qv, *cacc, *ccnt;
    __half *Pv, *Pc, *hc, *hv;
    cudaGetSymbolAddress((void**)&hc,   g_hc);
    cudaGetSymbolAddress((void**)&hv,   g_hv);
    cudaGetSymbolAddress((void**)&Pv,   g_Pv);
    cudaGetSymbolAddress((void**)&Pc,   g_Pc);
    cudaGetSymbolAddress((void**)&Qc,   g_Qc);
    cudaGetSymbolAddress((void**)&Qv,   g_Qv);
    cudaGetSymbolAddress((void**)&cacc, g_ctx_acc);
    cudaGetSymbolAddress((void**)&ccnt, g_ctx_cnt);

    int *deg, *fill, *bsum;
    uint4 *sedge1, *sedge2;
    cudaGetSymbolAddress((void**)&deg,    g_deg);
    cudaGetSymbolAddress((void**)&fill,   g_fill);
    cudaGetSymbolAddress((void**)&bsum,   g_bsum);
    cudaGetSymbolAddress((void**)&sedge1, g_sedge1);
    cudaGetSymbolAddress((void**)&sedge2, g_sedge2);

    float *Bvc, *Bcv, *Bc, *Bv;
    cudaGetSymbolAddress((void**)&Bvc, g_Bvc);
    cudaGetSymbolAddress((void**)&Bcv, g_Bcv);
    cudaGetSymbolAddress((void**)&Bc,  g_Bc);
    cudaGetSymbolAddress((void**)&Bv,  g_Bv);

    float* out = (float*)d_out;

    cudaFuncSetAttribute(tc_gemm, cudaFuncAttributeMaxDynamicSharedMemorySize,
                         SMEM_TOTAL_TC);

    const int nb = (NN + 4095) / 4096;   // scan blocks

    cudaStream_t s1;
    cudaStreamCreateWithFlags(&s1, cudaStreamNonBlocking);
    cudaEvent_t evZero, evPc, evPrep, evS1;
    cudaEventCreateWithFlags(&evZero, cudaEventDisableTiming);
    cudaEventCreateWithFlags(&evPc,   cudaEventDisableTiming);
    cudaEventCreateWithFlags(&evPrep, cudaEventDisableTiming);
    cudaEventCreateWithFlags(&evS1,   cudaEventDisableTiming);

    // ---- s0: zero, wprep, P GEMMs ----
    zero_small<<<512, 256>>>(deg, fill, cacc, ccnt);
    cudaEventRecord(evZero, 0);
    wprep<<<(102400 + 255) / 256, 256>>>(W_vc, W_cv, W_c, W_v);
    // P_v (TF32, fp16 out)
    tc_gemm<<<(NV + 63) / 64, 256, SMEM_TOTAL_TC>>>(
        NV, nullptr, 0, var_emb, 0, nullptr,
        Bvc, 128, nullptr, nullptr, nullptr, 0, nullptr, Pv);
    // P_c (TF32, fp16 out) <-- ncu control point
    tc_gemm<<<(NC + 63) / 64, 256, SMEM_TOTAL_TC>>>(
        NC, nullptr, 0, clause_emb, 0, nullptr,
        Bcv, 128, nullptr, nullptr, nullptr, 0, nullptr, Pc);
    cudaEventRecord(evPc, 0);

    // ---- s1: edge prep + Q precomputes, overlapped under P GEMMs ----
    cudaStreamWaitEvent(s1, evZero, 0);
    hist_kernel<<<(2 * E + 255) / 256, 256, 0, s1>>>(
        E, assigns_dst, contains_dst, deg);
    scanA<<<nb, 256, 0, s1>>>(deg, NN, deg, bsum);
    scanB<<<1, 32, 0, s1>>>(bsum, nb);
    scanC<<<(NN + 255) / 256, 256, 0, s1>>>(deg, bsum, NN);
    scatter_kernel<<<(2 * E + 255) / 256, 256, 0, s1>>>(
        E, assigns_src, assigns_dst, (const float4*)edge_sat_vc,
        contains_src, contains_dst, (const float4*)edge_sat_cv,
        deg, fill, sedge1, sedge2);
    fused_gemm<<<1, 256, 0, s1>>>(C_NU, ctx_emb, W_c + 144 * C_D, Qc);
    fused_gemm<<<1, 256, 0, s1>>>(C_NU, ctx_emb, W_v + 144 * C_D, Qv);
    cudaEventRecord(evPrep, s1);

    // ---- chain-C on s0: agg1 -> node_clause -> seg_mean_c ----
    cudaStreamWaitEvent(0, evPrep, 0);
    agg_kernel<<<(NC + 7) / 8, 256>>>(
        NC, 0, 0, deg, fill, sedge1, Pv, W_vc, b_vc, hc);
    tc_gemm<<<(NC + 63) / 64, 256, SMEM_TOTAL_TC>>>(
        NC, clause_feats, 16, hc, 1, clause_emb,
        Bc, 272, b_c, Qc, clause_ctx, 1, out, nullptr);
    seg_mean_ctx<<<2048, 128>>>(out, clause_ctx, NC, cacc, ccnt);

    // ---- chain-V on s1: agg2 -> node_var -> seg_mean_v ----
    // (evPrep is already in s1's stream order; only need Pc from s0)
    cudaStreamWaitEvent(s1, evPc, 0);
    agg_kernel<<<(NV + 7) / 8, 256, 0, s1>>>(
        NV, NC, E, deg, fill, sedge2, Pc, W_cv, b_cv, hv);
    tc_gemm<<<(NV + 63) / 64, 256, SMEM_TOTAL_TC, s1>>>(
        NV, var_feats, 16, hv, 1, var_emb,
        Bv, 272, b_v, Qv, var_ctx, 1, out + (size_t)NC * C_D, nullptr);
    seg_mean_ctx<<<2048, 128, 0, s1>>>(out + (size_t)NC * C_D, var_ctx, NV,
                                       cacc + C_NU * C_D, ccnt + C_NU);
    cudaEventRecord(evS1, s1);

    // ---- join, then final context update on s0 ----
    cudaStreamWaitEvent(0, evS1, 0);
    ctx_update<<<C_NU, 128>>>(ctx_feats, ctx_emb, cacc, ccnt, W_u, b_u,
                              out + (size_t)(NC + NV) * C_D);
}